// round 1
// baseline (speedup 1.0000x reference)
#include <cuda_runtime.h>
#include <cuda_bf16.h>
#include <math.h>

// Problem constants
#define TT   16384      // B*S tokens
#define DD   256        // model dim
#define HH   1024       // hidden dim
#define EE   8          // experts
#define BM   64         // tokens per FFN tile

// Scratch (static device globals; no allocations allowed)
__device__ int   g_counts[EE];
__device__ int   g_tok[EE * TT];
__device__ float g_wt [EE * TT];

__global__ void zero_counts_kernel() {
    if (threadIdx.x < EE) g_counts[threadIdx.x] = 0;
}

// ---------------------------------------------------------------------------
// Router: logits -> softmax -> probs out; top-2 -> renorm -> scatter to lists
// ---------------------------------------------------------------------------
__global__ __launch_bounds__(128) void router_kernel(
    const float* __restrict__ x,
    const float* __restrict__ wr,    // [D,E]
    const float* __restrict__ br,    // [E]
    float* __restrict__ probs_out)   // [T,E]
{
    __shared__ float wrs[DD * EE];   // 8 KB
    int tid = threadIdx.x;
    for (int i = tid; i < DD * EE; i += blockDim.x) wrs[i] = wr[i];
    __syncthreads();

    int t = blockIdx.x * blockDim.x + tid;
    if (t >= TT) return;

    float acc[EE];
#pragma unroll
    for (int e = 0; e < EE; e++) acc[e] = 0.f;

    const float* xr = x + (size_t)t * DD;
#pragma unroll 4
    for (int d = 0; d < DD; d++) {
        float xv = xr[d];
#pragma unroll
        for (int e = 0; e < EE; e++) acc[e] += xv * wrs[d * EE + e];
    }
#pragma unroll
    for (int e = 0; e < EE; e++) acc[e] += br[e];

    // softmax
    float mx = acc[0];
#pragma unroll
    for (int e = 1; e < EE; e++) mx = fmaxf(mx, acc[e]);
    float s = 0.f;
    float p[EE];
#pragma unroll
    for (int e = 0; e < EE; e++) { p[e] = __expf(acc[e] - mx); s += p[e]; }
    float inv = 1.f / s;
#pragma unroll
    for (int e = 0; e < EE; e++) {
        p[e] *= inv;
        probs_out[(size_t)t * EE + e] = p[e];
    }

    // top-2 (first occurrence on ties, matching lax.top_k)
    int i0 = 0; float v0 = p[0];
#pragma unroll
    for (int e = 1; e < EE; e++) if (p[e] > v0) { v0 = p[e]; i0 = e; }
    int i1 = -1; float v1 = -1.f;
#pragma unroll
    for (int e = 0; e < EE; e++) if (e != i0 && p[e] > v1) { v1 = p[e]; i1 = e; }

    float rs = 1.f / (v0 + v1);
    float w0 = v0 * rs, w1 = v1 * rs;

    int p0 = atomicAdd(&g_counts[i0], 1);
    g_tok[i0 * TT + p0] = t;
    g_wt [i0 * TT + p0] = w0;
    int p1 = atomicAdd(&g_counts[i1], 1);
    g_tok[i1 * TT + p1] = t;
    g_wt [i1 * TT + p1] = w1;
}

// ---------------------------------------------------------------------------
// Fused expert FFN: gather X tile -> GEMM1 -> exact GELU -> GEMM2 -> scatter
// Block: 256 threads (16x16). Tile: 64 tokens of one expert.
// smem: Xs[64][256] + hs[64][128] + Ws[8192] = 128 KB dynamic
// ---------------------------------------------------------------------------
__global__ __launch_bounds__(256, 1) void ffn_kernel(
    const float* __restrict__ x,
    const float* __restrict__ w1,   // [E,D,H]
    const float* __restrict__ b1,   // [E,H]
    const float* __restrict__ w2,   // [E,H,D]
    const float* __restrict__ b2,   // [E,D]
    float* __restrict__ out)        // [T,D]
{
    extern __shared__ float smem[];
    float* Xs = smem;                 // 64*256 = 16384 floats
    float* hs = Xs + BM * DD;         // 64*128 =  8192 floats
    float* Ws = hs + BM * 128;        //           8192 floats (W1/W2 tiles)
    __shared__ int   toks[BM];
    __shared__ float wts [BM];

    int tid = threadIdx.x;

    // map flat block id -> (expert, tile)
    int e = -1, tile = 0, cnt = 0;
    {
        int acc = 0;
#pragma unroll
        for (int i = 0; i < EE; i++) {
            int c  = g_counts[i];
            int nt = (c + BM - 1) / BM;
            if (e < 0 && (int)blockIdx.x < acc + nt) { e = i; tile = blockIdx.x - acc; cnt = c; }
            acc += nt;
        }
    }
    if (e < 0) return;
    int base = tile * BM;
    int m    = min(BM, cnt - base);

    if (tid < BM) {
        if (tid < m) {
            toks[tid] = g_tok[e * TT + base + tid];
            wts [tid] = g_wt [e * TT + base + tid];
        } else { toks[tid] = 0; wts[tid] = 0.f; }
    }
    __syncthreads();

    // gather X tile
    for (int idx = tid; idx < BM * DD; idx += 256) {
        int r = idx >> 8, d = idx & 255;
        Xs[idx] = (r < m) ? x[(size_t)toks[r] * DD + d] : 0.f;
    }
    __syncthreads();

    int ty = tid >> 4;   // 0..15 -> rows ty*4 .. ty*4+3
    int tx = tid & 15;   // 0..15 -> cols tx + 16*j

    float y[4][16];
#pragma unroll
    for (int i = 0; i < 4; i++)
#pragma unroll
        for (int j = 0; j < 16; j++) y[i][j] = 0.f;

    const float* w1e = w1 + (size_t)e * DD * HH;
    const float* w2e = w2 + (size_t)e * HH * DD;
    const float* b1e = b1 + (size_t)e * HH;
    const float* b2e = b2 + (size_t)e * DD;

    for (int hc = 0; hc < HH / 128; hc++) {
        // ---- GEMM1: acc1[64,128] = Xs[64,256] @ W1[:,hc*128:+128]
        float acc1[4][8];
#pragma unroll
        for (int i = 0; i < 4; i++)
#pragma unroll
            for (int j = 0; j < 8; j++) acc1[i][j] = 0.f;

        for (int kb = 0; kb < DD; kb += 64) {
            for (int idx = tid; idx < 64 * 128; idx += 256) {
                int kk = idx >> 7, c = idx & 127;
                Ws[idx] = w1e[(size_t)(kb + kk) * HH + hc * 128 + c];
            }
            __syncthreads();
#pragma unroll 4
            for (int kk = 0; kk < 64; kk++) {
                float a[4];
#pragma unroll
                for (int i = 0; i < 4; i++) a[i] = Xs[(ty * 4 + i) * DD + kb + kk];
                float bb[8];
#pragma unroll
                for (int j = 0; j < 8; j++) bb[j] = Ws[kk * 128 + tx + 16 * j];
#pragma unroll
                for (int i = 0; i < 4; i++)
#pragma unroll
                    for (int j = 0; j < 8; j++) acc1[i][j] = fmaf(a[i], bb[j], acc1[i][j]);
            }
            __syncthreads();
        }

        // ---- bias + exact GELU -> hs
#pragma unroll
        for (int i = 0; i < 4; i++)
#pragma unroll
            for (int j = 0; j < 8; j++) {
                int c = tx + 16 * j;
                float v = acc1[i][j] + b1e[hc * 128 + c];
                v = 0.5f * v * (1.f + erff(v * 0.70710678118654752f));
                hs[(ty * 4 + i) * 128 + c] = v;
            }
        __syncthreads();

        // ---- GEMM2 partial: y[64,256] += hs[64,128] @ W2[hc*128:+128, :]
        for (int k2 = 0; k2 < 128; k2 += 32) {
            for (int idx = tid; idx < 32 * 256; idx += 256) {
                int kk = idx >> 8, c = idx & 255;
                Ws[idx] = w2e[(size_t)(hc * 128 + k2 + kk) * DD + c];
            }
            __syncthreads();
#pragma unroll 4
            for (int kk = 0; kk < 32; kk++) {
                float a2[4];
#pragma unroll
                for (int i = 0; i < 4; i++) a2[i] = hs[(ty * 4 + i) * 128 + k2 + kk];
                float b2r[16];
#pragma unroll
                for (int j = 0; j < 16; j++) b2r[j] = Ws[kk * DD + tx + 16 * j];
#pragma unroll
                for (int i = 0; i < 4; i++)
#pragma unroll
                    for (int j = 0; j < 16; j++) y[i][j] = fmaf(a2[i], b2r[j], y[i][j]);
            }
            __syncthreads();
        }
    }

    // ---- weighted scatter-add: out[t] += w * (y + b2)
#pragma unroll
    for (int i = 0; i < 4; i++) {
        int r = ty * 4 + i;
        if (r < m) {
            int   t = toks[r];
            float w = wts[r];
            float* orow = out + (size_t)t * DD;
#pragma unroll
            for (int j = 0; j < 16; j++) {
                int c = tx + 16 * j;
                atomicAdd(&orow[c], w * (y[i][j] + b2e[c]));
            }
        }
    }
}

// ---------------------------------------------------------------------------
extern "C" void kernel_launch(void* const* d_in, const int* in_sizes, int n_in,
                              void* d_out, int out_size)
{
    const float* x  = (const float*)d_in[0];
    const float* wr = (const float*)d_in[1];
    const float* br = (const float*)d_in[2];
    const float* w1 = (const float*)d_in[3];
    const float* b1 = (const float*)d_in[4];
    const float* w2 = (const float*)d_in[5];
    const float* b2 = (const float*)d_in[6];
    float* out = (float*)d_out;                       // [T*D] then [T*E]
    float* probs_out = out + (size_t)TT * DD;

    cudaMemsetAsync(out, 0, (size_t)TT * DD * sizeof(float));
    zero_counts_kernel<<<1, 32>>>();
    router_kernel<<<TT / 128, 128>>>(x, wr, br, probs_out);

    const int smem_bytes = (BM * DD + BM * 128 + 8192) * sizeof(float); // 128 KB
    cudaFuncSetAttribute(ffn_kernel, cudaFuncAttributeMaxDynamicSharedMemorySize, smem_bytes);
    const int max_tiles = (2 * TT) / BM + EE;         // 520
    ffn_kernel<<<max_tiles, 256, smem_bytes>>>(x, w1, b1, w2, b2, out);
}

// round 2
// speedup vs baseline: 1.0518x; 1.0518x over previous
#include <cuda_runtime.h>
#include <cuda_bf16.h>
#include <math.h>

// Problem constants
#define TT   16384      // B*S tokens
#define DD   256        // model dim
#define HH   1024       // hidden dim
#define EE   8          // experts
#define BM   64         // tokens per FFN tile

// Scratch (static device globals; no allocations allowed)
__device__ int   g_counts[EE];
__device__ int   g_tok[EE * TT];
__device__ float g_wt [EE * TT];

__global__ void zero_counts_kernel() {
    if (threadIdx.x < EE) g_counts[threadIdx.x] = 0;
}

// ---------------------------------------------------------------------------
// Router: logits -> softmax -> probs out; top-2 -> renorm -> scatter to lists
// ---------------------------------------------------------------------------
__global__ __launch_bounds__(128) void router_kernel(
    const float* __restrict__ x,
    const float* __restrict__ wr,    // [D,E]
    const float* __restrict__ br,    // [E]
    float* __restrict__ probs_out)   // [T,E]
{
    __shared__ float wrs[DD * EE];   // 8 KB
    int tid = threadIdx.x;
    for (int i = tid; i < DD * EE; i += blockDim.x) wrs[i] = wr[i];
    __syncthreads();

    int t = blockIdx.x * blockDim.x + tid;
    if (t >= TT) return;

    float acc[EE];
#pragma unroll
    for (int e = 0; e < EE; e++) acc[e] = 0.f;

    const float* xr = x + (size_t)t * DD;
#pragma unroll 4
    for (int d = 0; d < DD; d++) {
        float xv = xr[d];
#pragma unroll
        for (int e = 0; e < EE; e++) acc[e] += xv * wrs[d * EE + e];
    }
#pragma unroll
    for (int e = 0; e < EE; e++) acc[e] += br[e];

    // softmax
    float mx = acc[0];
#pragma unroll
    for (int e = 1; e < EE; e++) mx = fmaxf(mx, acc[e]);
    float s = 0.f;
    float p[EE];
#pragma unroll
    for (int e = 0; e < EE; e++) { p[e] = __expf(acc[e] - mx); s += p[e]; }
    float inv = 1.f / s;
#pragma unroll
    for (int e = 0; e < EE; e++) {
        p[e] *= inv;
        probs_out[(size_t)t * EE + e] = p[e];
    }

    // top-2 (first occurrence on ties, matching lax.top_k)
    int i0 = 0; float v0 = p[0];
#pragma unroll
    for (int e = 1; e < EE; e++) if (p[e] > v0) { v0 = p[e]; i0 = e; }
    int i1 = -1; float v1 = -1.f;
#pragma unroll
    for (int e = 0; e < EE; e++) if (e != i0 && p[e] > v1) { v1 = p[e]; i1 = e; }

    float rs = 1.f / (v0 + v1);
    float w0 = v0 * rs, w1 = v1 * rs;

    int p0 = atomicAdd(&g_counts[i0], 1);
    g_tok[i0 * TT + p0] = t;
    g_wt [i0 * TT + p0] = w0;
    int p1 = atomicAdd(&g_counts[i1], 1);
    g_tok[i1 * TT + p1] = t;
    g_wt [i1 * TT + p1] = w1;
}

// ---------------------------------------------------------------------------
// Fused expert FFN: gather X tile -> GEMM1 -> exact GELU -> GEMM2 -> scatter
// Block: 256 threads (16x16). Tile: 64 tokens of one expert.
// smem: Xs[64][256] + hs[64][128] + Ws[8192] = 128 KB dynamic
// ---------------------------------------------------------------------------
__global__ __launch_bounds__(256, 1) void ffn_kernel(
    const float* __restrict__ x,
    const float* __restrict__ w1,   // [E,D,H]
    const float* __restrict__ b1,   // [E,H]
    const float* __restrict__ w2,   // [E,H,D]
    const float* __restrict__ b2,   // [E,D]
    float* __restrict__ out)        // [T,D]
{
    extern __shared__ float smem[];
    float* Xs = smem;                 // 64*256 = 16384 floats
    float* hs = Xs + BM * DD;         // 64*128 =  8192 floats
    float* Ws = hs + BM * 128;        //           8192 floats (W1/W2 tiles)
    __shared__ int   toks[BM];
    __shared__ float wts [BM];

    int tid = threadIdx.x;

    // map flat block id -> (expert, tile)
    int e = -1, tile = 0, cnt = 0;
    {
        int acc = 0;
#pragma unroll
        for (int i = 0; i < EE; i++) {
            int c  = g_counts[i];
            int nt = (c + BM - 1) / BM;
            if (e < 0 && (int)blockIdx.x < acc + nt) { e = i; tile = blockIdx.x - acc; cnt = c; }
            acc += nt;
        }
    }
    if (e < 0) return;
    int base = tile * BM;
    int m    = min(BM, cnt - base);

    if (tid < BM) {
        if (tid < m) {
            toks[tid] = g_tok[e * TT + base + tid];
            wts [tid] = g_wt [e * TT + base + tid];
        } else { toks[tid] = 0; wts[tid] = 0.f; }
    }
    __syncthreads();

    // gather X tile
    for (int idx = tid; idx < BM * DD; idx += 256) {
        int r = idx >> 8, d = idx & 255;
        Xs[idx] = (r < m) ? x[(size_t)toks[r] * DD + d] : 0.f;
    }
    __syncthreads();

    int ty = tid >> 4;   // 0..15 -> rows ty*4 .. ty*4+3
    int tx = tid & 15;   // 0..15 -> cols tx + 16*j

    float y[4][16];
#pragma unroll
    for (int i = 0; i < 4; i++)
#pragma unroll
        for (int j = 0; j < 16; j++) y[i][j] = 0.f;

    const float* w1e = w1 + (size_t)e * DD * HH;
    const float* w2e = w2 + (size_t)e * HH * DD;
    const float* b1e = b1 + (size_t)e * HH;
    const float* b2e = b2 + (size_t)e * DD;

    for (int hc = 0; hc < HH / 128; hc++) {
        // ---- GEMM1: acc1[64,128] = Xs[64,256] @ W1[:,hc*128:+128]
        float acc1[4][8];
#pragma unroll
        for (int i = 0; i < 4; i++)
#pragma unroll
            for (int j = 0; j < 8; j++) acc1[i][j] = 0.f;

        for (int kb = 0; kb < DD; kb += 64) {
            for (int idx = tid; idx < 64 * 128; idx += 256) {
                int kk = idx >> 7, c = idx & 127;
                Ws[idx] = w1e[(size_t)(kb + kk) * HH + hc * 128 + c];
            }
            __syncthreads();
#pragma unroll 4
            for (int kk = 0; kk < 64; kk++) {
                float a[4];
#pragma unroll
                for (int i = 0; i < 4; i++) a[i] = Xs[(ty * 4 + i) * DD + kb + kk];
                float bb[8];
#pragma unroll
                for (int j = 0; j < 8; j++) bb[j] = Ws[kk * 128 + tx + 16 * j];
#pragma unroll
                for (int i = 0; i < 4; i++)
#pragma unroll
                    for (int j = 0; j < 8; j++) acc1[i][j] = fmaf(a[i], bb[j], acc1[i][j]);
            }
            __syncthreads();
        }

        // ---- bias + exact GELU -> hs
#pragma unroll
        for (int i = 0; i < 4; i++)
#pragma unroll
            for (int j = 0; j < 8; j++) {
                int c = tx + 16 * j;
                float v = acc1[i][j] + b1e[hc * 128 + c];
                v = 0.5f * v * (1.f + erff(v * 0.70710678118654752f));
                hs[(ty * 4 + i) * 128 + c] = v;
            }
        __syncthreads();

        // ---- GEMM2 partial: y[64,256] += hs[64,128] @ W2[hc*128:+128, :]
        for (int k2 = 0; k2 < 128; k2 += 32) {
            for (int idx = tid; idx < 32 * 256; idx += 256) {
                int kk = idx >> 8, c = idx & 255;
                Ws[idx] = w2e[(size_t)(hc * 128 + k2 + kk) * DD + c];
            }
            __syncthreads();
#pragma unroll 4
            for (int kk = 0; kk < 32; kk++) {
                float a2[4];
#pragma unroll
                for (int i = 0; i < 4; i++) a2[i] = hs[(ty * 4 + i) * 128 + k2 + kk];
                float b2r[16];
#pragma unroll
                for (int j = 0; j < 16; j++) b2r[j] = Ws[kk * DD + tx + 16 * j];
#pragma unroll
                for (int i = 0; i < 4; i++)
#pragma unroll
                    for (int j = 0; j < 16; j++) y[i][j] = fmaf(a2[i], b2r[j], y[i][j]);
            }
            __syncthreads();
        }
    }

    // ---- weighted scatter-add: out[t] += w * (y + b2)
#pragma unroll
    for (int i = 0; i < 4; i++) {
        int r = ty * 4 + i;
        if (r < m) {
            int   t = toks[r];
            float w = wts[r];
            float* orow = out + (size_t)t * DD;
#pragma unroll
            for (int j = 0; j < 16; j++) {
                int c = tx + 16 * j;
                atomicAdd(&orow[c], w * (y[i][j] + b2e[c]));
            }
        }
    }
}

// ---------------------------------------------------------------------------
extern "C" void kernel_launch(void* const* d_in, const int* in_sizes, int n_in,
                              void* d_out, int out_size)
{
    const float* x  = (const float*)d_in[0];
    const float* wr = (const float*)d_in[1];
    const float* br = (const float*)d_in[2];
    const float* w1 = (const float*)d_in[3];
    const float* b1 = (const float*)d_in[4];
    const float* w2 = (const float*)d_in[5];
    const float* b2 = (const float*)d_in[6];
    float* out = (float*)d_out;                       // [T*D] then [T*E]
    float* probs_out = out + (size_t)TT * DD;

    cudaMemsetAsync(out, 0, (size_t)TT * DD * sizeof(float));
    zero_counts_kernel<<<1, 32>>>();
    router_kernel<<<TT / 128, 128>>>(x, wr, br, probs_out);

    const int smem_bytes = (BM * DD + BM * 128 + 8192) * sizeof(float); // 128 KB
    cudaFuncSetAttribute(ffn_kernel, cudaFuncAttributeMaxDynamicSharedMemorySize, smem_bytes);
    const int max_tiles = (2 * TT) / BM + EE;         // 520
    ffn_kernel<<<max_tiles, 256, smem_bytes>>>(x, w1, b1, w2, b2, out);
}

// round 4
// speedup vs baseline: 4.5266x; 4.3037x over previous
#include <cuda_runtime.h>
#include <cstdint>
#include <math.h>

#define TT 16384
#define DD 256
#define HH 1024
#define EE 8
#define BM 128

// strides (floats) chosen for conflict-free mma fragment LDS
#define XS_S  260   // mod 32 = 4
#define W1_S  40    // mod 32 = 8
#define W2_S  264   // mod 32 = 8
#define HS_S  36    // mod 32 = 4
#define SMEM_WORDS (128*XS_S + 256*W1_S + 32*W2_S + 128*HS_S)  // 56576
#define SMEM_BYTES (SMEM_WORDS*4)                              // 226304

__device__ int   g_counts[EE];
__device__ int   g_tok [EE*TT];
__device__ float g_wt  [EE*TT];
__device__ int   g_slot[EE*TT];
__device__ float g_contrib[2*TT*DD];
__device__ float g_w1t[EE*DD*HH];
__device__ float g_w2t[EE*HH*DD];

__device__ __forceinline__ uint32_t f2tf(float f) {
    uint32_t u; asm("cvt.rna.tf32.f32 %0, %1;" : "=r"(u) : "f"(f)); return u;
}
__device__ __forceinline__ uint32_t s2u(const void* p) {
    uint32_t a;
    asm("{ .reg .u64 t; cvta.to.shared.u64 t, %1; cvt.u32.u64 %0, t; }" : "=r"(a) : "l"(p));
    return a;
}
__device__ __forceinline__ void cpa16(uint32_t s, const void* g) {
    asm volatile("cp.async.cg.shared.global [%0], [%1], 16;" :: "r"(s), "l"(g));
}
#define CP_COMMIT() asm volatile("cp.async.commit_group;")
#define CP_WAIT0()  asm volatile("cp.async.wait_group 0;")

__device__ __forceinline__ void mma8(float& d0, float& d1, float& d2, float& d3,
                                     uint32_t a0, uint32_t a1, uint32_t a2, uint32_t a3,
                                     uint32_t b0, uint32_t b1) {
    asm volatile("mma.sync.aligned.m16n8k8.row.col.f32.tf32.tf32.f32 "
                 "{%0,%1,%2,%3}, {%4,%5,%6,%7}, {%8,%9}, {%0,%1,%2,%3};"
                 : "+f"(d0), "+f"(d1), "+f"(d2), "+f"(d3)
                 : "r"(a0), "r"(a1), "r"(a2), "r"(a3), "r"(b0), "r"(b1));
}

// ---------------- weight pre-round to tf32 ----------------------------------
__global__ __launch_bounds__(256) void convert_kernel(
    const float4* __restrict__ w1, const float4* __restrict__ w2)
{
    int i = blockIdx.x * 256 + threadIdx.x;          // EE*DD*HH/4 = 524288 total
    float4 a = __ldg(w1 + i), b = __ldg(w2 + i);
    uint4 ua, ub;
    ua.x = f2tf(a.x); ua.y = f2tf(a.y); ua.z = f2tf(a.z); ua.w = f2tf(a.w);
    ub.x = f2tf(b.x); ub.y = f2tf(b.y); ub.z = f2tf(b.z); ub.w = f2tf(b.w);
    ((uint4*)g_w1t)[i] = ua;
    ((uint4*)g_w2t)[i] = ub;
}

// ---------------- router: warp per token ------------------------------------
__global__ __launch_bounds__(256) void router_kernel(
    const float* __restrict__ x, const float* __restrict__ wr,
    const float* __restrict__ br, float* __restrict__ probs_out)
{
    int tid = threadIdx.x, lane = tid & 31;
    int t = (blockIdx.x * 256 + tid) >> 5;
    if (t >= TT) return;

    const float4* xr = (const float4*)(x + (size_t)t * DD + lane * 8);
    float4 x0 = __ldg(xr), x1 = __ldg(xr + 1);
    float xv[8] = {x0.x,x0.y,x0.z,x0.w,x1.x,x1.y,x1.z,x1.w};

    float l[EE];
#pragma unroll
    for (int e = 0; e < EE; e++) l[e] = 0.f;
    const float4* wrow = (const float4*)(wr + (size_t)(lane * 8) * EE);
#pragma unroll
    for (int j = 0; j < 8; j++) {
        float4 wa = __ldg(wrow + 2*j), wb = __ldg(wrow + 2*j + 1);
        l[0] = fmaf(xv[j], wa.x, l[0]); l[1] = fmaf(xv[j], wa.y, l[1]);
        l[2] = fmaf(xv[j], wa.z, l[2]); l[3] = fmaf(xv[j], wa.w, l[3]);
        l[4] = fmaf(xv[j], wb.x, l[4]); l[5] = fmaf(xv[j], wb.y, l[5]);
        l[6] = fmaf(xv[j], wb.z, l[6]); l[7] = fmaf(xv[j], wb.w, l[7]);
    }
#pragma unroll
    for (int off = 16; off > 0; off >>= 1)
#pragma unroll
        for (int e = 0; e < EE; e++) l[e] += __shfl_xor_sync(0xFFFFFFFF, l[e], off);

    if (lane) return;
#pragma unroll
    for (int e = 0; e < EE; e++) l[e] += __ldg(br + e);
    float mx = l[0];
#pragma unroll
    for (int e = 1; e < EE; e++) mx = fmaxf(mx, l[e]);
    float s = 0.f, p[EE];
#pragma unroll
    for (int e = 0; e < EE; e++) { p[e] = __expf(l[e] - mx); s += p[e]; }
    float inv = 1.f / s;
#pragma unroll
    for (int e = 0; e < EE; e++) p[e] *= inv;

    float4* po = (float4*)(probs_out + (size_t)t * EE);
    po[0] = make_float4(p[0],p[1],p[2],p[3]);
    po[1] = make_float4(p[4],p[5],p[6],p[7]);

    int i0 = 0; float v0 = p[0];
#pragma unroll
    for (int e = 1; e < EE; e++) if (p[e] > v0) { v0 = p[e]; i0 = e; }
    int i1 = -1; float v1 = -1.f;
#pragma unroll
    for (int e = 0; e < EE; e++) if (e != i0 && p[e] > v1) { v1 = p[e]; i1 = e; }
    float rs = 1.f / (v0 + v1);

    int p0 = atomicAdd(&g_counts[i0], 1);
    g_tok[i0*TT+p0] = t; g_wt[i0*TT+p0] = v0*rs; g_slot[i0*TT+p0] = 2*t;
    int p1 = atomicAdd(&g_counts[i1], 1);
    g_tok[i1*TT+p1] = t; g_wt[i1*TT+p1] = v1*rs; g_slot[i1*TT+p1] = 2*t+1;
}

// ---------------- FFN: mma.sync tf32 ----------------------------------------
__global__ __launch_bounds__(256, 1) void ffn_kernel(
    const float* __restrict__ xg,
    const float* __restrict__ b1g, const float* __restrict__ b2g)
{
    extern __shared__ uint32_t sm[];
    uint32_t* Xs  = sm;                    // [128][260]
    uint32_t* W1s = Xs  + 128*XS_S;        // [256][40]
    uint32_t* W2s = W1s + 256*W1_S;        // [32][264]
    uint32_t* Hs  = W2s + 32*W2_S;         // [128][36]
    __shared__ int toks[BM]; __shared__ float wts[BM]; __shared__ int slts[BM];

    int tid = threadIdx.x, wid = tid >> 5, lane = tid & 31;
    int qr = lane >> 2, qc = lane & 3;
    int wr = wid >> 1, wc = wid & 1;

    int e = -1, tile = 0, cnt = 0, acc = 0;
#pragma unroll
    for (int i = 0; i < EE; i++) {
        int c = g_counts[i], nt = (c + BM - 1) / BM;
        if (e < 0 && (int)blockIdx.x < acc + nt) { e = i; tile = blockIdx.x - acc; cnt = c; }
        acc += nt;
    }
    if (e < 0) return;
    int base = tile * BM, mval = min(BM, cnt - base);

    if (tid < BM) {
        if (tid < mval) {
            toks[tid] = g_tok [e*TT + base + tid];
            wts [tid] = g_wt  [e*TT + base + tid];
            slts[tid] = g_slot[e*TT + base + tid];
        } else { toks[tid] = 0; wts[tid] = 0.f; slts[tid] = 0; }
    }
    __syncthreads();

    const float* w1t = g_w1t + (size_t)e * DD * HH;
    const float* w2t = g_w2t + (size_t)e * HH * DD;
    const float* b1e = b1g + (size_t)e * HH;
    const float* b2e = b2g + (size_t)e * DD;

    // prologue: cp.async W1 chunk 0; gather+cvt X
#pragma unroll
    for (int i = 0; i < 8; i++) {
        int f = tid + i*256, row = f >> 3, seg = f & 7;
        cpa16(s2u(W1s + row*W1_S + seg*4), w1t + (size_t)row*HH + seg*4);
    }
    CP_COMMIT();
    for (int i4 = tid; i4 < BM*64; i4 += 256) {
        int r = i4 >> 6, c4 = i4 & 63;
        float4 v = (r < mval) ? __ldg((const float4*)(xg + (size_t)toks[r]*DD + c4*4))
                              : make_float4(0.f,0.f,0.f,0.f);
        uint4 u; u.x = f2tf(v.x); u.y = f2tf(v.y); u.z = f2tf(v.z); u.w = f2tf(v.w);
        *(uint4*)(Xs + r*XS_S + c4*4) = u;
    }
    CP_WAIT0();
    __syncthreads();

    float c2[2][16][4];
#pragma unroll
    for (int mt = 0; mt < 2; mt++)
#pragma unroll
        for (int nt = 0; nt < 16; nt++)
#pragma unroll
            for (int c = 0; c < 4; c++) c2[mt][nt][c] = 0.f;

    for (int hc = 0; hc < 32; hc++) {
        // prefetch W2 chunk hc (used in this chunk's GEMM2)
#pragma unroll
        for (int i = 0; i < 8; i++) {
            int f = tid + i*256, row = f >> 6, seg = f & 63;
            cpa16(s2u(W2s + row*W2_S + seg*4), w2t + (size_t)(hc*32 + row)*DD + seg*4);
        }
        CP_COMMIT();

        // ---- GEMM1: C1[128,32] = X[128,256] @ W1chunk; warp tile 32x16
        float c1[2][2][4];
#pragma unroll
        for (int mt = 0; mt < 2; mt++)
#pragma unroll
            for (int nt = 0; nt < 2; nt++)
#pragma unroll
                for (int c = 0; c < 4; c++) c1[mt][nt][c] = 0.f;

        const uint32_t* xb0 = Xs + (wr*32 + qr)*XS_S + qc;
        const uint32_t* xb1 = Xs + (wr*32 + 16 + qr)*XS_S + qc;
        const uint32_t* w1b = W1s + qc*W1_S + wc*16 + qr;
#pragma unroll 8
        for (int ks = 0; ks < 32; ks++) {
            int k0 = ks * 8;
            uint32_t a00 = xb0[k0],   a01 = xb0[k0 + 8*XS_S];
            uint32_t a02 = xb0[k0+4], a03 = xb0[k0 + 8*XS_S + 4];
            uint32_t a10 = xb1[k0],   a11 = xb1[k0 + 8*XS_S];
            uint32_t a12 = xb1[k0+4], a13 = xb1[k0 + 8*XS_S + 4];
            uint32_t b00 = w1b[k0*W1_S],     b01 = w1b[(k0+4)*W1_S];
            uint32_t b10 = w1b[k0*W1_S + 8], b11 = w1b[(k0+4)*W1_S + 8];
            mma8(c1[0][0][0],c1[0][0][1],c1[0][0][2],c1[0][0][3], a00,a01,a02,a03, b00,b01);
            mma8(c1[0][1][0],c1[0][1][1],c1[0][1][2],c1[0][1][3], a00,a01,a02,a03, b10,b11);
            mma8(c1[1][0][0],c1[1][0][1],c1[1][0][2],c1[1][0][3], a10,a11,a12,a13, b00,b01);
            mma8(c1[1][1][0],c1[1][1][1],c1[1][1][2],c1[1][1][3], a10,a11,a12,a13, b10,b11);
        }

        // ---- bias + exact GELU -> Hs (tf32)
#pragma unroll
        for (int mt = 0; mt < 2; mt++)
#pragma unroll
            for (int nt = 0; nt < 2; nt++) {
                int col = wc*16 + nt*8 + 2*qc;
                float bb0 = __ldg(b1e + hc*32 + col);
                float bb1 = __ldg(b1e + hc*32 + col + 1);
                int r = wr*32 + mt*16 + qr;
                float v0 = c1[mt][nt][0] + bb0, v1 = c1[mt][nt][1] + bb1;
                float v2 = c1[mt][nt][2] + bb0, v3 = c1[mt][nt][3] + bb1;
                v0 = 0.5f*v0*(1.f + erff(v0*0.70710678f));
                v1 = 0.5f*v1*(1.f + erff(v1*0.70710678f));
                v2 = 0.5f*v2*(1.f + erff(v2*0.70710678f));
                v3 = 0.5f*v3*(1.f + erff(v3*0.70710678f));
                uint2 lo, hi;
                lo.x = f2tf(v0); lo.y = f2tf(v1);
                hi.x = f2tf(v2); hi.y = f2tf(v3);
                *(uint2*)(Hs + r*HS_S + col)       = lo;
                *(uint2*)(Hs + (r+8)*HS_S + col)   = hi;
            }
        CP_WAIT0();
        __syncthreads();

        // prefetch W1 chunk hc+1 (overlaps GEMM2)
        if (hc < 31) {
#pragma unroll
            for (int i = 0; i < 8; i++) {
                int f = tid + i*256, row = f >> 3, seg = f & 7;
                cpa16(s2u(W1s + row*W1_S + seg*4),
                      w1t + (size_t)row*HH + (hc+1)*32 + seg*4);
            }
        }
        CP_COMMIT();

        // ---- GEMM2: C2[128,256] += H[128,32] @ W2chunk; warp tile 32x128
        const uint32_t* hb0 = Hs + (wr*32 + qr)*HS_S + qc;
        const uint32_t* hb1 = Hs + (wr*32 + 16 + qr)*HS_S + qc;
        const uint32_t* w2b = W2s + qc*W2_S + wc*128 + qr;
#pragma unroll
        for (int ks = 0; ks < 4; ks++) {
            int k0 = ks * 8;
            uint32_t a00 = hb0[k0],   a01 = hb0[k0 + 8*HS_S];
            uint32_t a02 = hb0[k0+4], a03 = hb0[k0 + 8*HS_S + 4];
            uint32_t a10 = hb1[k0],   a11 = hb1[k0 + 8*HS_S];
            uint32_t a12 = hb1[k0+4], a13 = hb1[k0 + 8*HS_S + 4];
#pragma unroll
            for (int nt = 0; nt < 16; nt++) {
                uint32_t bv0 = w2b[k0*W2_S + nt*8];
                uint32_t bv1 = w2b[(k0+4)*W2_S + nt*8];
                mma8(c2[0][nt][0],c2[0][nt][1],c2[0][nt][2],c2[0][nt][3],
                     a00,a01,a02,a03, bv0,bv1);
                mma8(c2[1][nt][0],c2[1][nt][1],c2[1][nt][2],c2[1][nt][3],
                     a10,a11,a12,a13, bv0,bv1);
            }
        }
        CP_WAIT0();
        __syncthreads();
    }

    // ---- epilogue: contrib[slot] = w * (y + b2)
#pragma unroll
    for (int mt = 0; mt < 2; mt++)
#pragma unroll
        for (int half = 0; half < 2; half++) {
            int r = wr*32 + mt*16 + qr + half*8;
            if (r < mval) {
                float w = wts[r];
                float* crow = g_contrib + (size_t)slts[r] * DD;
#pragma unroll
                for (int nt = 0; nt < 16; nt++) {
                    int col = wc*128 + nt*8 + 2*qc;
                    float2 o;
                    o.x = w * (c2[mt][nt][half*2+0] + __ldg(b2e + col));
                    o.y = w * (c2[mt][nt][half*2+1] + __ldg(b2e + col + 1));
                    *(float2*)(crow + col) = o;
                }
            }
        }
}

// ---------------- combine + counter reset -----------------------------------
__global__ __launch_bounds__(256) void combine_kernel(float* __restrict__ out)
{
    int g = blockIdx.x * 256 + threadIdx.x;
    int t = g >> 6, q = g & 63;
    const float4* c4 = (const float4*)g_contrib;
    float4 a = c4[(size_t)(2*t) * 64 + q];
    float4 b = c4[(size_t)(2*t+1) * 64 + q];
    ((float4*)out)[g] = make_float4(a.x+b.x, a.y+b.y, a.z+b.z, a.w+b.w);
    if (g < EE) g_counts[g] = 0;
}

extern "C" void kernel_launch(void* const* d_in, const int* in_sizes, int n_in,
                              void* d_out, int out_size)
{
    const float* x  = (const float*)d_in[0];
    const float* wr = (const float*)d_in[1];
    const float* br = (const float*)d_in[2];
    const float* w1 = (const float*)d_in[3];
    const float* b1 = (const float*)d_in[4];
    const float* w2 = (const float*)d_in[5];
    const float* b2 = (const float*)d_in[6];
    float* out = (float*)d_out;
    float* probs_out = out + (size_t)TT * DD;

    convert_kernel<<<(EE*DD*HH/4)/256, 256>>>((const float4*)w1, (const float4*)w2);
    router_kernel<<<TT/8, 256>>>(x, wr, br, probs_out);

    cudaFuncSetAttribute(ffn_kernel, cudaFuncAttributeMaxDynamicSharedMemorySize, SMEM_BYTES);
    ffn_kernel<<<(2*TT)/BM + EE, 256, SMEM_BYTES>>>(x, b1, b2);

    combine_kernel<<<(TT*DD/4)/256, 256>>>(out);
}

// round 6
// speedup vs baseline: 6.3166x; 1.3954x over previous
#include <cuda_runtime.h>
#include <cuda_fp16.h>
#include <cstdint>
#include <math.h>

#define TT 16384
#define DD 256
#define HH 1024
#define EE 8
#define BM 128

// smem row strides in halves (bank-conflict-free for ldmatrix)
#define XS_S 264
#define W1_S 264
#define W2_S 40
#define HS_S 40
#define XS_N (128*XS_S)
#define W1_N (32*W1_S)
#define W2_N (256*W2_S)
#define HS_N (128*HS_S)
#define SMEM_BYTES ((XS_N+W1_N+W2_N+HS_N)*2)   // 115200

__device__ int    g_counts[EE];
__device__ int    g_tok [EE*TT];
__device__ float  g_wt  [EE*TT];
__device__ int    g_slot[EE*TT];
__device__ float  g_contrib[2*TT*DD];
__device__ __half g_w1t[EE*HH*DD];   // [E][H][D] fp16
__device__ __half g_w2t[EE*DD*HH];   // [E][D][H] fp16

__device__ __forceinline__ uint32_t s2u(const void* p) {
    uint32_t a;
    asm("{ .reg .u64 t; cvta.to.shared.u64 t, %1; cvt.u32.u64 %0, t; }" : "=r"(a) : "l"(p));
    return a;
}
__device__ __forceinline__ void cpa16(uint32_t s, const void* g) {
    asm volatile("cp.async.cg.shared.global [%0], [%1], 16;" :: "r"(s), "l"(g));
}
#define CP_COMMIT() asm volatile("cp.async.commit_group;")
#define CP_WAIT0()  asm volatile("cp.async.wait_group 0;")

__device__ __forceinline__ void ldsm4(uint32_t& r0, uint32_t& r1, uint32_t& r2,
                                      uint32_t& r3, uint32_t a) {
    asm volatile("ldmatrix.sync.aligned.m8n8.x4.shared.b16 {%0,%1,%2,%3}, [%4];"
                 : "=r"(r0), "=r"(r1), "=r"(r2), "=r"(r3) : "r"(a));
}
__device__ __forceinline__ void mma16(float* c, const uint32_t* a,
                                      uint32_t b0, uint32_t b1) {
    asm volatile("mma.sync.aligned.m16n8k16.row.col.f32.f16.f16.f32 "
                 "{%0,%1,%2,%3}, {%4,%5,%6,%7}, {%8,%9}, {%0,%1,%2,%3};"
                 : "+f"(c[0]), "+f"(c[1]), "+f"(c[2]), "+f"(c[3])
                 : "r"(a[0]), "r"(a[1]), "r"(a[2]), "r"(a[3]), "r"(b0), "r"(b1));
}

// ---- transpose + fp16 convert: dst[N][M] = in[M][N]; dst picked in DEVICE code
__global__ __launch_bounds__(256) void transpose_kernel(
    const float* __restrict__ in, int M, int N, int which)
{
    __shared__ float tile[32][33];
    __half* outp = which ? g_w2t : g_w1t;      // device-side symbol reference
    int ntj = N >> 5;
    int b = blockIdx.x, e = blockIdx.y;
    int ti = b / ntj, tj = b % ntj;
    const float* ine = in + (size_t)e * M * N;
    __half* oute = outp + (size_t)e * M * N;
    int c = threadIdx.x & 31, r8 = threadIdx.x >> 5;
#pragma unroll
    for (int it = 0; it < 4; it++) {
        int r = it * 8 + r8;
        tile[r][c] = __ldg(ine + (size_t)(ti*32 + r) * N + tj*32 + c);
    }
    __syncthreads();
#pragma unroll
    for (int it = 0; it < 4; it++) {
        int r = it * 8 + r8;
        oute[(size_t)(tj*32 + r) * M + ti*32 + c] = __float2half_rn(tile[c][r]);
    }
}

// ---------------- router: warp per token ------------------------------------
__global__ __launch_bounds__(256) void router_kernel(
    const float* __restrict__ x, const float* __restrict__ wr,
    const float* __restrict__ br, float* __restrict__ probs_out)
{
    int tid = threadIdx.x, lane = tid & 31;
    int t = (blockIdx.x * 256 + tid) >> 5;
    if (t >= TT) return;

    const float4* xr = (const float4*)(x + (size_t)t * DD + lane * 8);
    float4 x0 = __ldg(xr), x1 = __ldg(xr + 1);
    float xv[8] = {x0.x,x0.y,x0.z,x0.w,x1.x,x1.y,x1.z,x1.w};

    float l[EE];
#pragma unroll
    for (int e = 0; e < EE; e++) l[e] = 0.f;
    const float4* wrow = (const float4*)(wr + (size_t)(lane * 8) * EE);
#pragma unroll
    for (int j = 0; j < 8; j++) {
        float4 wa = __ldg(wrow + 2*j), wb = __ldg(wrow + 2*j + 1);
        l[0] = fmaf(xv[j], wa.x, l[0]); l[1] = fmaf(xv[j], wa.y, l[1]);
        l[2] = fmaf(xv[j], wa.z, l[2]); l[3] = fmaf(xv[j], wa.w, l[3]);
        l[4] = fmaf(xv[j], wb.x, l[4]); l[5] = fmaf(xv[j], wb.y, l[5]);
        l[6] = fmaf(xv[j], wb.z, l[6]); l[7] = fmaf(xv[j], wb.w, l[7]);
    }
#pragma unroll
    for (int off = 16; off > 0; off >>= 1)
#pragma unroll
        for (int e = 0; e < EE; e++) l[e] += __shfl_xor_sync(0xFFFFFFFF, l[e], off);

    if (lane) return;
#pragma unroll
    for (int e = 0; e < EE; e++) l[e] += __ldg(br + e);
    float mx = l[0];
#pragma unroll
    for (int e = 1; e < EE; e++) mx = fmaxf(mx, l[e]);
    float s = 0.f, p[EE];
#pragma unroll
    for (int e = 0; e < EE; e++) { p[e] = __expf(l[e] - mx); s += p[e]; }
    float inv = 1.f / s;
#pragma unroll
    for (int e = 0; e < EE; e++) p[e] *= inv;

    float4* po = (float4*)(probs_out + (size_t)t * EE);
    po[0] = make_float4(p[0],p[1],p[2],p[3]);
    po[1] = make_float4(p[4],p[5],p[6],p[7]);

    int i0 = 0; float v0 = p[0];
#pragma unroll
    for (int e = 1; e < EE; e++) if (p[e] > v0) { v0 = p[e]; i0 = e; }
    int i1 = -1; float v1 = -1.f;
#pragma unroll
    for (int e = 0; e < EE; e++) if (e != i0 && p[e] > v1) { v1 = p[e]; i1 = e; }
    float rs = 1.f / (v0 + v1);

    int p0 = atomicAdd(&g_counts[i0], 1);
    g_tok[i0*TT+p0] = t; g_wt[i0*TT+p0] = v0*rs; g_slot[i0*TT+p0] = 2*t;
    int p1 = atomicAdd(&g_counts[i1], 1);
    g_tok[i1*TT+p1] = t; g_wt[i1*TT+p1] = v1*rs; g_slot[i1*TT+p1] = 2*t+1;
}

// ---------------- FFN: fp16 mma.sync + ldmatrix -----------------------------
__global__ __launch_bounds__(256, 1) void ffn_kernel(
    const float* __restrict__ xg,
    const float* __restrict__ b1g, const float* __restrict__ b2g)
{
    extern __shared__ __half sh[];
    __half* Xs  = sh;
    __half* W1s = Xs  + XS_N;
    __half* W2s = W1s + W1_N;
    __half* Hs  = W2s + W2_N;
    __shared__ int toks[BM]; __shared__ float wts[BM]; __shared__ int slts[BM];

    int tid = threadIdx.x, wid = tid >> 5, lane = tid & 31;
    int qr = lane >> 2, qc = lane & 3;
    int wr = wid >> 1, wc = wid & 1;

    int e = -1, tile = 0, cnt = 0, acc = 0;
#pragma unroll
    for (int i = 0; i < EE; i++) {
        int c = g_counts[i], nt = (c + BM - 1) / BM;
        if (e < 0 && (int)blockIdx.x < acc + nt) { e = i; tile = blockIdx.x - acc; cnt = c; }
        acc += nt;
    }
    if (e < 0) return;
    int base = tile * BM, mval = min(BM, cnt - base);

    if (tid < BM) {
        if (tid < mval) {
            toks[tid] = g_tok [e*TT + base + tid];
            wts [tid] = g_wt  [e*TT + base + tid];
            slts[tid] = g_slot[e*TT + base + tid];
        } else { toks[tid] = 0; wts[tid] = 0.f; slts[tid] = 0; }
    }
    __syncthreads();

    const __half* w1te = g_w1t + (size_t)e * HH * DD;   // [H][D]
    const __half* w2te = g_w2t + (size_t)e * DD * HH;   // [D][H]
    const float*  b1e  = b1g + (size_t)e * HH;
    const float*  b2e  = b2g + (size_t)e * DD;

    uint32_t xs_b = s2u(Xs), w1_b = s2u(W1s), w2_b = s2u(W2s), hs_b = s2u(Hs);

    // prologue: W1 chunk 0 (rows h=0..31, 512B each)
#pragma unroll
    for (int i = 0; i < 4; i++) {
        int f = tid + i*256, row = f >> 5, seg = f & 31;
        cpa16(w1_b + (uint32_t)(row*W1_S*2 + seg*16), w1te + (size_t)row*DD + seg*8);
    }
    CP_COMMIT();
    // gather + cvt X
    for (int i4 = tid; i4 < BM*64; i4 += 256) {
        int r = i4 >> 6, c4 = i4 & 63;
        float4 v = (r < mval) ? __ldg((const float4*)(xg + (size_t)toks[r]*DD + c4*4))
                              : make_float4(0.f,0.f,0.f,0.f);
        __half2 h0 = __floats2half2_rn(v.x, v.y);
        __half2 h1 = __floats2half2_rn(v.z, v.w);
        uint2 u;
        u.x = *reinterpret_cast<uint32_t*>(&h0);
        u.y = *reinterpret_cast<uint32_t*>(&h1);
        *reinterpret_cast<uint2*>(Xs + r*XS_S + c4*4) = u;
    }
    CP_WAIT0();
    __syncthreads();

    float c2[2][16][4];
#pragma unroll
    for (int mt = 0; mt < 2; mt++)
#pragma unroll
        for (int nt = 0; nt < 16; nt++)
#pragma unroll
            for (int c = 0; c < 4; c++) c2[mt][nt][c] = 0.f;

    // ldmatrix address components
    int a_row = lane & 15, a_kof = 8 * (lane >> 4);            // A tiles
    int b_row = ((lane >> 4) << 3) + (lane & 7);               // B n within pair
    int b_kof = 8 * ((lane >> 3) & 1);

    for (int hc = 0; hc < 32; hc++) {
        // prefetch W2 chunk hc (rows d=0..255, 64B each)
#pragma unroll
        for (int i = 0; i < 4; i++) {
            int f = tid + i*256, row = f >> 2, seg = f & 3;
            cpa16(w2_b + (uint32_t)(row*W2_S*2 + seg*16),
                  w2te + (size_t)row*HH + hc*32 + seg*8);
        }
        CP_COMMIT();

        // ---- GEMM1: C1[128,32] = X[128,256] @ W1c ; warp tile 32x16
        float c1[2][2][4];
#pragma unroll
        for (int mt = 0; mt < 2; mt++)
#pragma unroll
            for (int nt = 0; nt < 2; nt++)
#pragma unroll
                for (int c = 0; c < 4; c++) c1[mt][nt][c] = 0.f;

#pragma unroll 4
        for (int ks = 0; ks < 16; ks++) {
            int k0 = ks * 16;
            uint32_t a0[4], a1[4], b[4];
            ldsm4(a0[0],a0[1],a0[2],a0[3],
                  xs_b + (uint32_t)(((wr*32 + a_row)*XS_S + k0 + a_kof) * 2));
            ldsm4(a1[0],a1[1],a1[2],a1[3],
                  xs_b + (uint32_t)(((wr*32 + 16 + a_row)*XS_S + k0 + a_kof) * 2));
            ldsm4(b[0],b[1],b[2],b[3],
                  w1_b + (uint32_t)(((wc*16 + b_row)*W1_S + k0 + b_kof) * 2));
            mma16(c1[0][0], a0, b[0], b[1]);
            mma16(c1[0][1], a0, b[2], b[3]);
            mma16(c1[1][0], a1, b[0], b[1]);
            mma16(c1[1][1], a1, b[2], b[3]);
        }

        // ---- bias + exact GELU -> Hs (fp16)
#pragma unroll
        for (int mt = 0; mt < 2; mt++)
#pragma unroll
            for (int nt = 0; nt < 2; nt++) {
                int col = wc*16 + nt*8 + 2*qc;
                float bb0 = __ldg(b1e + hc*32 + col);
                float bb1 = __ldg(b1e + hc*32 + col + 1);
                int r = wr*32 + mt*16 + qr;
                float v0 = c1[mt][nt][0] + bb0, v1 = c1[mt][nt][1] + bb1;
                float v2 = c1[mt][nt][2] + bb0, v3 = c1[mt][nt][3] + bb1;
                v0 = 0.5f*v0*(1.f + erff(v0*0.70710678f));
                v1 = 0.5f*v1*(1.f + erff(v1*0.70710678f));
                v2 = 0.5f*v2*(1.f + erff(v2*0.70710678f));
                v3 = 0.5f*v3*(1.f + erff(v3*0.70710678f));
                *reinterpret_cast<__half2*>(Hs + r*HS_S + col)     = __floats2half2_rn(v0, v1);
                *reinterpret_cast<__half2*>(Hs + (r+8)*HS_S + col) = __floats2half2_rn(v2, v3);
            }
        CP_WAIT0();
        __syncthreads();

        // prefetch W1 chunk hc+1 (overlaps GEMM2)
        if (hc < 31) {
#pragma unroll
            for (int i = 0; i < 4; i++) {
                int f = tid + i*256, row = f >> 5, seg = f & 31;
                cpa16(w1_b + (uint32_t)(row*W1_S*2 + seg*16),
                      w1te + (size_t)((hc+1)*32 + row)*DD + seg*8);
            }
        }
        CP_COMMIT();

        // ---- GEMM2: C2[128,256] += H[128,32] @ W2c ; warp tile 32x128
#pragma unroll
        for (int ks = 0; ks < 2; ks++) {
            int k0 = ks * 16;
            uint32_t a0[4], a1[4];
            ldsm4(a0[0],a0[1],a0[2],a0[3],
                  hs_b + (uint32_t)(((wr*32 + a_row)*HS_S + k0 + a_kof) * 2));
            ldsm4(a1[0],a1[1],a1[2],a1[3],
                  hs_b + (uint32_t)(((wr*32 + 16 + a_row)*HS_S + k0 + a_kof) * 2));
#pragma unroll
            for (int p = 0; p < 8; p++) {
                uint32_t b[4];
                ldsm4(b[0],b[1],b[2],b[3],
                      w2_b + (uint32_t)(((wc*128 + p*16 + b_row)*W2_S + k0 + b_kof) * 2));
                mma16(c2[0][2*p],   a0, b[0], b[1]);
                mma16(c2[0][2*p+1], a0, b[2], b[3]);
                mma16(c2[1][2*p],   a1, b[0], b[1]);
                mma16(c2[1][2*p+1], a1, b[2], b[3]);
            }
        }
        CP_WAIT0();
        __syncthreads();
    }

    // ---- epilogue: contrib[slot] = w * (y + b2)
#pragma unroll
    for (int mt = 0; mt < 2; mt++)
#pragma unroll
        for (int half = 0; half < 2; half++) {
            int r = wr*32 + mt*16 + qr + half*8;
            if (r < mval) {
                float w = wts[r];
                float* crow = g_contrib + (size_t)slts[r] * DD;
#pragma unroll
                for (int nt = 0; nt < 16; nt++) {
                    int col = wc*128 + nt*8 + 2*qc;
                    float2 o;
                    o.x = w * (c2[mt][nt][half*2+0] + __ldg(b2e + col));
                    o.y = w * (c2[mt][nt][half*2+1] + __ldg(b2e + col + 1));
                    *(float2*)(crow + col) = o;
                }
            }
        }
}

// ---------------- combine + counter reset -----------------------------------
__global__ __launch_bounds__(256) void combine_kernel(float* __restrict__ out)
{
    int g = blockIdx.x * 256 + threadIdx.x;
    int t = g >> 6, q = g & 63;
    const float4* c4 = (const float4*)g_contrib;
    float4 a = c4[(size_t)(2*t) * 64 + q];
    float4 b = c4[(size_t)(2*t+1) * 64 + q];
    ((float4*)out)[g] = make_float4(a.x+b.x, a.y+b.y, a.z+b.z, a.w+b.w);
    if (g < EE) g_counts[g] = 0;
}

extern "C" void kernel_launch(void* const* d_in, const int* in_sizes, int n_in,
                              void* d_out, int out_size)
{
    const float* x  = (const float*)d_in[0];
    const float* wr = (const float*)d_in[1];
    const float* br = (const float*)d_in[2];
    const float* w1 = (const float*)d_in[3];
    const float* b1 = (const float*)d_in[4];
    const float* w2 = (const float*)d_in[5];
    const float* b2 = (const float*)d_in[6];
    float* out = (float*)d_out;
    float* probs_out = out + (size_t)TT * DD;

    transpose_kernel<<<dim3(256, EE), 256>>>(w1, DD, HH, 0);   // g_w1t = [H][D]
    transpose_kernel<<<dim3(256, EE), 256>>>(w2, HH, DD, 1);   // g_w2t = [D][H]
    router_kernel<<<TT/8, 256>>>(x, wr, br, probs_out);

    cudaFuncSetAttribute(ffn_kernel, cudaFuncAttributeMaxDynamicSharedMemorySize, SMEM_BYTES);
    ffn_kernel<<<(2*TT)/BM + EE, 256, SMEM_BYTES>>>(x, b1, b2);

    combine_kernel<<<(TT*DD/4)/256, 256>>>(out);
}

// round 7
// speedup vs baseline: 6.6837x; 1.0581x over previous
#include <cuda_runtime.h>
#include <cuda_fp16.h>
#include <cstdint>
#include <math.h>

#define TT 16384
#define DD 256
#define HH 1024
#define EE 8
#define BM 64

// smem row strides in halves (bank-conflict-free for ldmatrix)
#define XS_S 264
#define W1_S 264
#define W2_S 40
#define HS_S 40
#define XS_N (64*XS_S)
#define W1_N (32*W1_S)
#define W2_N (256*W2_S)
#define HS_N (64*HS_S)
#define SMEM_BYTES ((XS_N+W1_N+W2_N+HS_N)*2)   // 76288

__device__ int    g_counts[EE];
__device__ int    g_tok [EE*TT];
__device__ float  g_wt  [EE*TT];
__device__ int    g_slot[EE*TT];
__device__ float  g_contrib[2*TT*DD];
__device__ __half g_w1t[EE*HH*DD];   // [E][H][D] fp16
__device__ __half g_w2t[EE*DD*HH];   // [E][D][H] fp16

__device__ __forceinline__ uint32_t s2u(const void* p) {
    uint32_t a;
    asm("{ .reg .u64 t; cvta.to.shared.u64 t, %1; cvt.u32.u64 %0, t; }" : "=r"(a) : "l"(p));
    return a;
}
__device__ __forceinline__ void cpa16(uint32_t s, const void* g) {
    asm volatile("cp.async.cg.shared.global [%0], [%1], 16;" :: "r"(s), "l"(g));
}
#define CP_COMMIT() asm volatile("cp.async.commit_group;")
#define CP_WAIT0()  asm volatile("cp.async.wait_group 0;")

__device__ __forceinline__ void ldsm4(uint32_t& r0, uint32_t& r1, uint32_t& r2,
                                      uint32_t& r3, uint32_t a) {
    asm volatile("ldmatrix.sync.aligned.m8n8.x4.shared.b16 {%0,%1,%2,%3}, [%4];"
                 : "=r"(r0), "=r"(r1), "=r"(r2), "=r"(r3) : "r"(a));
}
__device__ __forceinline__ void mma16(float* c, const uint32_t* a,
                                      uint32_t b0, uint32_t b1) {
    asm volatile("mma.sync.aligned.m16n8k16.row.col.f32.f16.f16.f32 "
                 "{%0,%1,%2,%3}, {%4,%5,%6,%7}, {%8,%9}, {%0,%1,%2,%3};"
                 : "+f"(c[0]), "+f"(c[1]), "+f"(c[2]), "+f"(c[3])
                 : "r"(a[0]), "r"(a[1]), "r"(a[2]), "r"(a[3]), "r"(b0), "r"(b1));
}

// ---- transpose + fp16 convert: dst[N][M] = in[M][N]; dst picked in DEVICE code
__global__ __launch_bounds__(256) void transpose_kernel(
    const float* __restrict__ in, int M, int N, int which)
{
    __shared__ float tile[32][33];
    __half* outp = which ? g_w2t : g_w1t;
    int ntj = N >> 5;
    int b = blockIdx.x, e = blockIdx.y;
    int ti = b / ntj, tj = b % ntj;
    const float* ine = in + (size_t)e * M * N;
    __half* oute = outp + (size_t)e * M * N;
    int c = threadIdx.x & 31, r8 = threadIdx.x >> 5;
#pragma unroll
    for (int it = 0; it < 4; it++) {
        int r = it * 8 + r8;
        tile[r][c] = __ldg(ine + (size_t)(ti*32 + r) * N + tj*32 + c);
    }
    __syncthreads();
#pragma unroll
    for (int it = 0; it < 4; it++) {
        int r = it * 8 + r8;
        oute[(size_t)(tj*32 + r) * M + ti*32 + c] = __float2half_rn(tile[c][r]);
    }
}

// ---------------- router: warp per token ------------------------------------
__global__ __launch_bounds__(256) void router_kernel(
    const float* __restrict__ x, const float* __restrict__ wr,
    const float* __restrict__ br, float* __restrict__ probs_out)
{
    int tid = threadIdx.x, lane = tid & 31;
    int t = (blockIdx.x * 256 + tid) >> 5;
    if (t >= TT) return;

    const float4* xr = (const float4*)(x + (size_t)t * DD + lane * 8);
    float4 x0 = __ldg(xr), x1 = __ldg(xr + 1);
    float xv[8] = {x0.x,x0.y,x0.z,x0.w,x1.x,x1.y,x1.z,x1.w};

    float l[EE];
#pragma unroll
    for (int e = 0; e < EE; e++) l[e] = 0.f;
    const float4* wrow = (const float4*)(wr + (size_t)(lane * 8) * EE);
#pragma unroll
    for (int j = 0; j < 8; j++) {
        float4 wa = __ldg(wrow + 2*j), wb = __ldg(wrow + 2*j + 1);
        l[0] = fmaf(xv[j], wa.x, l[0]); l[1] = fmaf(xv[j], wa.y, l[1]);
        l[2] = fmaf(xv[j], wa.z, l[2]); l[3] = fmaf(xv[j], wa.w, l[3]);
        l[4] = fmaf(xv[j], wb.x, l[4]); l[5] = fmaf(xv[j], wb.y, l[5]);
        l[6] = fmaf(xv[j], wb.z, l[6]); l[7] = fmaf(xv[j], wb.w, l[7]);
    }
#pragma unroll
    for (int off = 16; off > 0; off >>= 1)
#pragma unroll
        for (int e = 0; e < EE; e++) l[e] += __shfl_xor_sync(0xFFFFFFFF, l[e], off);

    if (lane) return;
#pragma unroll
    for (int e = 0; e < EE; e++) l[e] += __ldg(br + e);
    float mx = l[0];
#pragma unroll
    for (int e = 1; e < EE; e++) mx = fmaxf(mx, l[e]);
    float s = 0.f, p[EE];
#pragma unroll
    for (int e = 0; e < EE; e++) { p[e] = __expf(l[e] - mx); s += p[e]; }
    float inv = 1.f / s;
#pragma unroll
    for (int e = 0; e < EE; e++) p[e] *= inv;

    float4* po = (float4*)(probs_out + (size_t)t * EE);
    po[0] = make_float4(p[0],p[1],p[2],p[3]);
    po[1] = make_float4(p[4],p[5],p[6],p[7]);

    int i0 = 0; float v0 = p[0];
#pragma unroll
    for (int e = 1; e < EE; e++) if (p[e] > v0) { v0 = p[e]; i0 = e; }
    int i1 = -1; float v1 = -1.f;
#pragma unroll
    for (int e = 0; e < EE; e++) if (e != i0 && p[e] > v1) { v1 = p[e]; i1 = e; }
    float rs = 1.f / (v0 + v1);

    int p0 = atomicAdd(&g_counts[i0], 1);
    g_tok[i0*TT+p0] = t; g_wt[i0*TT+p0] = v0*rs; g_slot[i0*TT+p0] = 2*t;
    int p1 = atomicAdd(&g_counts[i1], 1);
    g_tok[i1*TT+p1] = t; g_wt[i1*TT+p1] = v1*rs; g_slot[i1*TT+p1] = 2*t+1;
}

// ---------------- FFN: fp16 mma.sync, 2 CTAs/SM -----------------------------
__global__ __launch_bounds__(256, 2) void ffn_kernel(
    const float* __restrict__ xg,
    const float* __restrict__ b1g, const float* __restrict__ b2g)
{
    extern __shared__ __half sh[];
    __half* Xs  = sh;
    __half* W1s = Xs  + XS_N;
    __half* W2s = W1s + W1_N;
    __half* Hs  = W2s + W2_N;
    __shared__ int toks[BM]; __shared__ float wts[BM]; __shared__ int slts[BM];

    int tid = threadIdx.x, wid = tid >> 5, lane = tid & 31;
    int qr = lane >> 2, qc = lane & 3;
    int wr = wid & 3, wc = wid >> 2;   // 4 M-groups x 2 N-halves

    int e = -1, tile = 0, cnt = 0, acc = 0;
#pragma unroll
    for (int i = 0; i < EE; i++) {
        int c = g_counts[i], nt = (c + BM - 1) / BM;
        if (e < 0 && (int)blockIdx.x < acc + nt) { e = i; tile = blockIdx.x - acc; cnt = c; }
        acc += nt;
    }
    if (e < 0) return;
    int base = tile * BM, mval = min(BM, cnt - base);

    if (tid < BM) {
        if (tid < mval) {
            toks[tid] = g_tok [e*TT + base + tid];
            wts [tid] = g_wt  [e*TT + base + tid];
            slts[tid] = g_slot[e*TT + base + tid];
        } else { toks[tid] = 0; wts[tid] = 0.f; slts[tid] = 0; }
    }
    __syncthreads();

    const __half* w1te = g_w1t + (size_t)e * HH * DD;   // [H][D]
    const __half* w2te = g_w2t + (size_t)e * DD * HH;   // [D][H]
    const float*  b1e  = b1g + (size_t)e * HH;
    const float*  b2e  = b2g + (size_t)e * DD;

    uint32_t xs_b = s2u(Xs), w1_b = s2u(W1s), w2_b = s2u(W2s), hs_b = s2u(Hs);

    // prologue: W1 chunk 0 (32 rows x 512B)
#pragma unroll
    for (int i = 0; i < 4; i++) {
        int f = tid + i*256, row = f >> 5, seg = f & 31;
        cpa16(w1_b + (uint32_t)(row*W1_S*2 + seg*16), w1te + (size_t)row*DD + seg*8);
    }
    CP_COMMIT();
    // gather + cvt X [64,256]
    for (int i4 = tid; i4 < BM*64; i4 += 256) {
        int r = i4 >> 6, c4 = i4 & 63;
        float4 v = (r < mval) ? __ldg((const float4*)(xg + (size_t)toks[r]*DD + c4*4))
                              : make_float4(0.f,0.f,0.f,0.f);
        __half2 h0 = __floats2half2_rn(v.x, v.y);
        __half2 h1 = __floats2half2_rn(v.z, v.w);
        uint2 u;
        u.x = *reinterpret_cast<uint32_t*>(&h0);
        u.y = *reinterpret_cast<uint32_t*>(&h1);
        *reinterpret_cast<uint2*>(Xs + r*XS_S + c4*4) = u;
    }
    CP_WAIT0();
    __syncthreads();

    float c2[16][4];
#pragma unroll
    for (int nt = 0; nt < 16; nt++)
#pragma unroll
        for (int c = 0; c < 4; c++) c2[nt][c] = 0.f;

    int a_row = lane & 15, a_kof = 8 * (lane >> 4);
    int b_row = ((lane >> 4) << 3) + (lane & 7);
    int b_kof = 8 * ((lane >> 3) & 1);

    for (int hc = 0; hc < 32; hc++) {
        // prefetch W2 chunk hc (256 rows x 64B)
#pragma unroll
        for (int i = 0; i < 4; i++) {
            int f = tid + i*256, row = f >> 2, seg = f & 3;
            cpa16(w2_b + (uint32_t)(row*W2_S*2 + seg*16),
                  w2te + (size_t)row*HH + hc*32 + seg*8);
        }
        CP_COMMIT();

        // ---- GEMM1: C1[64,32] = X[64,256] @ W1c ; warp tile 16x16
        float c1[2][4];
#pragma unroll
        for (int nt = 0; nt < 2; nt++)
#pragma unroll
            for (int c = 0; c < 4; c++) c1[nt][c] = 0.f;

#pragma unroll 8
        for (int ks = 0; ks < 16; ks++) {
            int k0 = ks * 16;
            uint32_t a[4], b[4];
            ldsm4(a[0],a[1],a[2],a[3],
                  xs_b + (uint32_t)(((wr*16 + a_row)*XS_S + k0 + a_kof) * 2));
            ldsm4(b[0],b[1],b[2],b[3],
                  w1_b + (uint32_t)(((wc*16 + b_row)*W1_S + k0 + b_kof) * 2));
            mma16(c1[0], a, b[0], b[1]);
            mma16(c1[1], a, b[2], b[3]);
        }

        // ---- bias + exact GELU -> Hs (fp16)
#pragma unroll
        for (int nt = 0; nt < 2; nt++) {
            int col = wc*16 + nt*8 + 2*qc;
            float bb0 = __ldg(b1e + hc*32 + col);
            float bb1 = __ldg(b1e + hc*32 + col + 1);
            int r = wr*16 + qr;
            float v0 = c1[nt][0] + bb0, v1 = c1[nt][1] + bb1;
            float v2 = c1[nt][2] + bb0, v3 = c1[nt][3] + bb1;
            v0 = 0.5f*v0*(1.f + erff(v0*0.70710678f));
            v1 = 0.5f*v1*(1.f + erff(v1*0.70710678f));
            v2 = 0.5f*v2*(1.f + erff(v2*0.70710678f));
            v3 = 0.5f*v3*(1.f + erff(v3*0.70710678f));
            *reinterpret_cast<__half2*>(Hs + r*HS_S + col)     = __floats2half2_rn(v0, v1);
            *reinterpret_cast<__half2*>(Hs + (r+8)*HS_S + col) = __floats2half2_rn(v2, v3);
        }
        CP_WAIT0();
        __syncthreads();

        // prefetch W1 chunk hc+1 (overlaps GEMM2)
        if (hc < 31) {
#pragma unroll
            for (int i = 0; i < 4; i++) {
                int f = tid + i*256, row = f >> 5, seg = f & 31;
                cpa16(w1_b + (uint32_t)(row*W1_S*2 + seg*16),
                      w1te + (size_t)((hc+1)*32 + row)*DD + seg*8);
            }
        }
        CP_COMMIT();

        // ---- GEMM2: C2[64,256] += H[64,32] @ W2c ; warp tile 16x128
#pragma unroll
        for (int ks = 0; ks < 2; ks++) {
            int k0 = ks * 16;
            uint32_t a[4];
            ldsm4(a[0],a[1],a[2],a[3],
                  hs_b + (uint32_t)(((wr*16 + a_row)*HS_S + k0 + a_kof) * 2));
#pragma unroll
            for (int p = 0; p < 8; p++) {
                uint32_t b[4];
                ldsm4(b[0],b[1],b[2],b[3],
                      w2_b + (uint32_t)(((wc*128 + p*16 + b_row)*W2_S + k0 + b_kof) * 2));
                mma16(c2[2*p],   a, b[0], b[1]);
                mma16(c2[2*p+1], a, b[2], b[3]);
            }
        }
        CP_WAIT0();
        __syncthreads();
    }

    // ---- epilogue: contrib[slot] = w * (y + b2)
#pragma unroll
    for (int half = 0; half < 2; half++) {
        int r = wr*16 + qr + half*8;
        if (r < mval) {
            float w = wts[r];
            float* crow = g_contrib + (size_t)slts[r] * DD;
#pragma unroll
            for (int nt = 0; nt < 16; nt++) {
                int col = wc*128 + nt*8 + 2*qc;
                float2 o;
                o.x = w * (c2[nt][half*2+0] + __ldg(b2e + col));
                o.y = w * (c2[nt][half*2+1] + __ldg(b2e + col + 1));
                *(float2*)(crow + col) = o;
            }
        }
    }
}

// ---------------- combine + counter reset -----------------------------------
__global__ __launch_bounds__(256) void combine_kernel(float* __restrict__ out)
{
    int g = blockIdx.x * 256 + threadIdx.x;
    int t = g >> 6, q = g & 63;
    const float4* c4 = (const float4*)g_contrib;
    float4 a = c4[(size_t)(2*t) * 64 + q];
    float4 b = c4[(size_t)(2*t+1) * 64 + q];
    ((float4*)out)[g] = make_float4(a.x+b.x, a.y+b.y, a.z+b.z, a.w+b.w);
    if (g < EE) g_counts[g] = 0;
}

extern "C" void kernel_launch(void* const* d_in, const int* in_sizes, int n_in,
                              void* d_out, int out_size)
{
    const float* x  = (const float*)d_in[0];
    const float* wr = (const float*)d_in[1];
    const float* br = (const float*)d_in[2];
    const float* w1 = (const float*)d_in[3];
    const float* b1 = (const float*)d_in[4];
    const float* w2 = (const float*)d_in[5];
    const float* b2 = (const float*)d_in[6];
    float* out = (float*)d_out;
    float* probs_out = out + (size_t)TT * DD;

    transpose_kernel<<<dim3(256, EE), 256>>>(w1, DD, HH, 0);   // g_w1t = [H][D]
    transpose_kernel<<<dim3(256, EE), 256>>>(w2, HH, DD, 1);   // g_w2t = [D][H]
    router_kernel<<<TT/8, 256>>>(x, wr, br, probs_out);

    cudaFuncSetAttribute(ffn_kernel, cudaFuncAttributeMaxDynamicSharedMemorySize, SMEM_BYTES);
    ffn_kernel<<<(2*TT)/BM + EE, 256, SMEM_BYTES>>>(x, b1, b2);

    combine_kernel<<<(TT*DD/4)/256, 256>>>(out);
}

// round 8
// speedup vs baseline: 7.3737x; 1.1032x over previous
#include <cuda_runtime.h>
#include <cuda_fp16.h>
#include <cstdint>
#include <math.h>

#define TT 16384
#define DD 256
#define HH 1024
#define EE 8
#define BM 64
#define HC 64
#define NCH (HH/HC)   // 16

// smem byte offsets (dynamic smem base)
#define XS_OFF  0u        // X:  64 rows x 512B, swizzled
#define W1_OFF  32768u    // W1c: 64 rows x 512B, swizzled   [n][k=256]
#define W2_OFF  65536u    // W2c: 256 rows x 144B (stride 72 halves) [n][k=64]
#define HS_OFF  102400u   // Hs: 64 rows x 144B
#define W2_S 72
#define HS_S 72
#define SMEM_BYTES 111616

// 16B-granule XOR swizzle for 512B rows (bits 4..6 ^= row&7)
#define SWZ512(byte, row) ((byte) ^ (((row) & 7) << 4))

__device__ int    g_counts[EE];
__device__ int    g_tok [EE*TT];
__device__ float  g_wt  [EE*TT];
__device__ int    g_slot[EE*TT];
__device__ float  g_contrib[2*TT*DD];
__device__ __half g_w1t[EE*HH*DD];   // [E][H][D] fp16
__device__ __half g_w2t[EE*DD*HH];   // [E][D][H] fp16

__device__ __forceinline__ uint32_t s2u(const void* p) {
    uint32_t a;
    asm("{ .reg .u64 t; cvta.to.shared.u64 t, %1; cvt.u32.u64 %0, t; }" : "=r"(a) : "l"(p));
    return a;
}
__device__ __forceinline__ void cpa16(uint32_t s, const void* g) {
    asm volatile("cp.async.cg.shared.global [%0], [%1], 16;" :: "r"(s), "l"(g));
}
#define CP_COMMIT() asm volatile("cp.async.commit_group;")
#define CP_WAIT0()  asm volatile("cp.async.wait_group 0;")

__device__ __forceinline__ void ldsm4(uint32_t& r0, uint32_t& r1, uint32_t& r2,
                                      uint32_t& r3, uint32_t a) {
    asm volatile("ldmatrix.sync.aligned.m8n8.x4.shared.b16 {%0,%1,%2,%3}, [%4];"
                 : "=r"(r0), "=r"(r1), "=r"(r2), "=r"(r3) : "r"(a));
}
__device__ __forceinline__ void mma16(float* c, const uint32_t* a,
                                      uint32_t b0, uint32_t b1) {
    asm volatile("mma.sync.aligned.m16n8k16.row.col.f32.f16.f16.f32 "
                 "{%0,%1,%2,%3}, {%4,%5,%6,%7}, {%8,%9}, {%0,%1,%2,%3};"
                 : "+f"(c[0]), "+f"(c[1]), "+f"(c[2]), "+f"(c[3])
                 : "r"(a[0]), "r"(a[1]), "r"(a[2]), "r"(a[3]), "r"(b0), "r"(b1));
}

// ---- transpose + fp16 convert: dst[N][M] = in[M][N]; dst picked in DEVICE code
__global__ __launch_bounds__(256) void transpose_kernel(
    const float* __restrict__ in, int M, int N, int which)
{
    __shared__ float tile[32][33];
    __half* outp = which ? g_w2t : g_w1t;
    int ntj = N >> 5;
    int b = blockIdx.x, e = blockIdx.y;
    int ti = b / ntj, tj = b % ntj;
    const float* ine = in + (size_t)e * M * N;
    __half* oute = outp + (size_t)e * M * N;
    int c = threadIdx.x & 31, r8 = threadIdx.x >> 5;
#pragma unroll
    for (int it = 0; it < 4; it++) {
        int r = it * 8 + r8;
        tile[r][c] = __ldg(ine + (size_t)(ti*32 + r) * N + tj*32 + c);
    }
    __syncthreads();
#pragma unroll
    for (int it = 0; it < 4; it++) {
        int r = it * 8 + r8;
        oute[(size_t)(tj*32 + r) * M + ti*32 + c] = __float2half_rn(tile[c][r]);
    }
}

// ---------------- router: warp per token ------------------------------------
__global__ __launch_bounds__(256) void router_kernel(
    const float* __restrict__ x, const float* __restrict__ wr,
    const float* __restrict__ br, float* __restrict__ probs_out)
{
    int tid = threadIdx.x, lane = tid & 31;
    int t = (blockIdx.x * 256 + tid) >> 5;
    if (t >= TT) return;

    const float4* xr = (const float4*)(x + (size_t)t * DD + lane * 8);
    float4 x0 = __ldg(xr), x1 = __ldg(xr + 1);
    float xv[8] = {x0.x,x0.y,x0.z,x0.w,x1.x,x1.y,x1.z,x1.w};

    float l[EE];
#pragma unroll
    for (int e = 0; e < EE; e++) l[e] = 0.f;
    const float4* wrow = (const float4*)(wr + (size_t)(lane * 8) * EE);
#pragma unroll
    for (int j = 0; j < 8; j++) {
        float4 wa = __ldg(wrow + 2*j), wb = __ldg(wrow + 2*j + 1);
        l[0] = fmaf(xv[j], wa.x, l[0]); l[1] = fmaf(xv[j], wa.y, l[1]);
        l[2] = fmaf(xv[j], wa.z, l[2]); l[3] = fmaf(xv[j], wa.w, l[3]);
        l[4] = fmaf(xv[j], wb.x, l[4]); l[5] = fmaf(xv[j], wb.y, l[5]);
        l[6] = fmaf(xv[j], wb.z, l[6]); l[7] = fmaf(xv[j], wb.w, l[7]);
    }
#pragma unroll
    for (int off = 16; off > 0; off >>= 1)
#pragma unroll
        for (int e = 0; e < EE; e++) l[e] += __shfl_xor_sync(0xFFFFFFFF, l[e], off);

    if (lane) return;
#pragma unroll
    for (int e = 0; e < EE; e++) l[e] += __ldg(br + e);
    float mx = l[0];
#pragma unroll
    for (int e = 1; e < EE; e++) mx = fmaxf(mx, l[e]);
    float s = 0.f, p[EE];
#pragma unroll
    for (int e = 0; e < EE; e++) { p[e] = __expf(l[e] - mx); s += p[e]; }
    float inv = 1.f / s;
#pragma unroll
    for (int e = 0; e < EE; e++) p[e] *= inv;

    float4* po = (float4*)(probs_out + (size_t)t * EE);
    po[0] = make_float4(p[0],p[1],p[2],p[3]);
    po[1] = make_float4(p[4],p[5],p[6],p[7]);

    int i0 = 0; float v0 = p[0];
#pragma unroll
    for (int e = 1; e < EE; e++) if (p[e] > v0) { v0 = p[e]; i0 = e; }
    int i1 = -1; float v1 = -1.f;
#pragma unroll
    for (int e = 0; e < EE; e++) if (e != i0 && p[e] > v1) { v1 = p[e]; i1 = e; }
    float rs = 1.f / (v0 + v1);

    int p0 = atomicAdd(&g_counts[i0], 1);
    g_tok[i0*TT+p0] = t; g_wt[i0*TT+p0] = v0*rs; g_slot[i0*TT+p0] = 2*t;
    int p1 = atomicAdd(&g_counts[i1], 1);
    g_tok[i1*TT+p1] = t; g_wt[i1*TT+p1] = v1*rs; g_slot[i1*TT+p1] = 2*t+1;
}

// ---------------- FFN: fp16 mma.sync, HC=64, swizzled tiles -----------------
__global__ __launch_bounds__(256, 2) void ffn_kernel(
    const float* __restrict__ xg,
    const float* __restrict__ b1g, const float* __restrict__ b2g)
{
    extern __shared__ char sh[];
    __shared__ int toks[BM]; __shared__ float wts[BM]; __shared__ int slts[BM];

    int tid = threadIdx.x, wid = tid >> 5, lane = tid & 31;
    int qr = lane >> 2, qc = lane & 3;
    int wr = wid & 3, wc = wid >> 2;     // GEMM1: 4 M-groups x 2 N-halves
    int wr2 = wid & 1, wc2 = wid >> 1;   // GEMM2: 2 M-groups x 4 N-quarters

    int e = -1, tile = 0, cnt = 0, acc = 0;
#pragma unroll
    for (int i = 0; i < EE; i++) {
        int c = g_counts[i], nt = (c + BM - 1) / BM;
        if (e < 0 && (int)blockIdx.x < acc + nt) { e = i; tile = blockIdx.x - acc; cnt = c; }
        acc += nt;
    }
    if (e < 0) return;
    int base = tile * BM, mval = min(BM, cnt - base);

    if (tid < BM) {
        if (tid < mval) {
            toks[tid] = g_tok [e*TT + base + tid];
            wts [tid] = g_wt  [e*TT + base + tid];
            slts[tid] = g_slot[e*TT + base + tid];
        } else { toks[tid] = 0; wts[tid] = 0.f; slts[tid] = 0; }
    }
    __syncthreads();

    const __half* w1te = g_w1t + (size_t)e * HH * DD;   // [H][D]
    const __half* w2te = g_w2t + (size_t)e * DD * HH;   // [D][H]
    const float*  b1e  = b1g + (size_t)e * HH;
    const float*  b2e  = b2g + (size_t)e * DD;

    uint32_t smb = s2u(sh);
    uint32_t xs_b = smb + XS_OFF, w1_b = smb + W1_OFF;
    uint32_t w2_b = smb + W2_OFF, hs_b = smb + HS_OFF;

    // prologue: W1 chunk 0 (64 rows x 512B, swizzled)
#pragma unroll
    for (int i = 0; i < 8; i++) {
        int f = tid + i*256, row = f >> 5, seg = f & 31;
        cpa16(w1_b + (uint32_t)(row*512 + SWZ512(seg*16, row)),
              w1te + (size_t)row*DD + seg*8);
    }
    CP_COMMIT();
    // gather + cvt X [64,256] into swizzled rows
    for (int i4 = tid; i4 < BM*64; i4 += 256) {
        int r = i4 >> 6, c4 = i4 & 63;
        float4 v = (r < mval) ? __ldg((const float4*)(xg + (size_t)toks[r]*DD + c4*4))
                              : make_float4(0.f,0.f,0.f,0.f);
        __half2 h0 = __floats2half2_rn(v.x, v.y);
        __half2 h1 = __floats2half2_rn(v.z, v.w);
        uint2 u;
        u.x = *reinterpret_cast<uint32_t*>(&h0);
        u.y = *reinterpret_cast<uint32_t*>(&h1);
        *reinterpret_cast<uint2*>(sh + XS_OFF + r*512 + SWZ512(c4*8, r)) = u;
    }
    CP_WAIT0();
    __syncthreads();

    float c2[2][8][4];
#pragma unroll
    for (int mt = 0; mt < 2; mt++)
#pragma unroll
        for (int nt = 0; nt < 8; nt++)
#pragma unroll
            for (int c = 0; c < 4; c++) c2[mt][nt][c] = 0.f;

    int a_row = lane & 15, a_kof = 8 * (lane >> 4);
    int b_row = ((lane >> 4) << 3) + (lane & 7);
    int b_kof = 8 * ((lane >> 3) & 1);

    for (int hc = 0; hc < NCH; hc++) {
        // prefetch W2 chunk hc (256 rows x 128B, stride 144B)
#pragma unroll
        for (int i = 0; i < 8; i++) {
            int f = tid + i*256, row = f >> 3, seg = f & 7;
            cpa16(w2_b + (uint32_t)(row*(W2_S*2) + seg*16),
                  w2te + (size_t)row*HH + hc*HC + seg*8);
        }
        CP_COMMIT();

        // ---- GEMM1: C1[64,64] = X[64,256] @ W1c ; warp tile 16x32
        float c1[4][4];
#pragma unroll
        for (int nt = 0; nt < 4; nt++)
#pragma unroll
            for (int c = 0; c < 4; c++) c1[nt][c] = 0.f;

#pragma unroll 8
        for (int ks = 0; ks < 16; ks++) {
            int k0 = ks * 16;
            uint32_t a[4], b0[4], b1r[4];
            {
                int row = wr*16 + a_row;
                ldsm4(a[0],a[1],a[2],a[3],
                      xs_b + (uint32_t)(row*512 + SWZ512((k0 + a_kof)*2, row)));
            }
            {
                int row = wc*32 + b_row;
                ldsm4(b0[0],b0[1],b0[2],b0[3],
                      w1_b + (uint32_t)(row*512 + SWZ512((k0 + b_kof)*2, row)));
                row += 16;
                ldsm4(b1r[0],b1r[1],b1r[2],b1r[3],
                      w1_b + (uint32_t)(row*512 + SWZ512((k0 + b_kof)*2, row)));
            }
            mma16(c1[0], a, b0[0], b0[1]);
            mma16(c1[1], a, b0[2], b0[3]);
            mma16(c1[2], a, b1r[0], b1r[1]);
            mma16(c1[3], a, b1r[2], b1r[3]);
        }
        CP_WAIT0();    // W2 chunk ready

        // ---- bias + exact GELU -> Hs
#pragma unroll
        for (int nt = 0; nt < 4; nt++) {
            int col = wc*32 + nt*8 + 2*qc;
            float bb0 = __ldg(b1e + hc*HC + col);
            float bb1 = __ldg(b1e + hc*HC + col + 1);
            int r = wr*16 + qr;
            float v0 = c1[nt][0] + bb0, v1 = c1[nt][1] + bb1;
            float v2 = c1[nt][2] + bb0, v3 = c1[nt][3] + bb1;
            v0 = 0.5f*v0*(1.f + erff(v0*0.70710678f));
            v1 = 0.5f*v1*(1.f + erff(v1*0.70710678f));
            v2 = 0.5f*v2*(1.f + erff(v2*0.70710678f));
            v3 = 0.5f*v3*(1.f + erff(v3*0.70710678f));
            *reinterpret_cast<__half2*>(sh + HS_OFF + (r*HS_S + col)*2)
                = __floats2half2_rn(v0, v1);
            *reinterpret_cast<__half2*>(sh + HS_OFF + ((r+8)*HS_S + col)*2)
                = __floats2half2_rn(v2, v3);
        }
        __syncthreads();   // Hs + W2 visible to all

        // prefetch W1 chunk hc+1 (overlaps GEMM2)
        if (hc + 1 < NCH) {
#pragma unroll
            for (int i = 0; i < 8; i++) {
                int f = tid + i*256, row = f >> 5, seg = f & 31;
                cpa16(w1_b + (uint32_t)(row*512 + SWZ512(seg*16, row)),
                      w1te + (size_t)((hc+1)*HC + row)*DD + seg*8);
            }
        }
        CP_COMMIT();

        // ---- GEMM2: C2[64,256] += H[64,64] @ W2c ; warp tile 32x64
#pragma unroll
        for (int ks = 0; ks < 4; ks++) {
            int k0 = ks * 16;
            uint32_t a0[4], a1[4];
            ldsm4(a0[0],a0[1],a0[2],a0[3],
                  hs_b + (uint32_t)(((wr2*32 + a_row)*HS_S + k0 + a_kof) * 2));
            ldsm4(a1[0],a1[1],a1[2],a1[3],
                  hs_b + (uint32_t)(((wr2*32 + 16 + a_row)*HS_S + k0 + a_kof) * 2));
#pragma unroll
            for (int p = 0; p < 4; p++) {
                uint32_t b[4];
                ldsm4(b[0],b[1],b[2],b[3],
                      w2_b + (uint32_t)(((wc2*64 + p*16 + b_row)*W2_S + k0 + b_kof) * 2));
                mma16(c2[0][2*p],   a0, b[0], b[1]);
                mma16(c2[0][2*p+1], a0, b[2], b[3]);
                mma16(c2[1][2*p],   a1, b[0], b[1]);
                mma16(c2[1][2*p+1], a1, b[2], b[3]);
            }
        }
        CP_WAIT0();    // W1 next ready
        __syncthreads();
    }

    // ---- epilogue: contrib[slot] = w * (y + b2)
#pragma unroll
    for (int mt = 0; mt < 2; mt++)
#pragma unroll
        for (int half = 0; half < 2; half++) {
            int r = wr2*32 + mt*16 + qr + half*8;
            if (r < mval) {
                float w = wts[r];
                float* crow = g_contrib + (size_t)slts[r] * DD;
#pragma unroll
                for (int nt = 0; nt < 8; nt++) {
                    int col = wc2*64 + nt*8 + 2*qc;
                    float2 o;
                    o.x = w * (c2[mt][nt][half*2+0] + __ldg(b2e + col));
                    o.y = w * (c2[mt][nt][half*2+1] + __ldg(b2e + col + 1));
                    *(float2*)(crow + col) = o;
                }
            }
        }
}

// ---------------- combine + counter reset -----------------------------------
__global__ __launch_bounds__(256) void combine_kernel(float* __restrict__ out)
{
    int g = blockIdx.x * 256 + threadIdx.x;
    int t = g >> 6, q = g & 63;
    const float4* c4 = (const float4*)g_contrib;
    float4 a = c4[(size_t)(2*t) * 64 + q];
    float4 b = c4[(size_t)(2*t+1) * 64 + q];
    ((float4*)out)[g] = make_float4(a.x+b.x, a.y+b.y, a.z+b.z, a.w+b.w);
    if (g < EE) g_counts[g] = 0;
}

extern "C" void kernel_launch(void* const* d_in, const int* in_sizes, int n_in,
                              void* d_out, int out_size)
{
    const float* x  = (const float*)d_in[0];
    const float* wr = (const float*)d_in[1];
    const float* br = (const float*)d_in[2];
    const float* w1 = (const float*)d_in[3];
    const float* b1 = (const float*)d_in[4];
    const float* w2 = (const float*)d_in[5];
    const float* b2 = (const float*)d_in[6];
    float* out = (float*)d_out;
    float* probs_out = out + (size_t)TT * DD;

    transpose_kernel<<<dim3(256, EE), 256>>>(w1, DD, HH, 0);   // g_w1t = [H][D]
    transpose_kernel<<<dim3(256, EE), 256>>>(w2, HH, DD, 1);   // g_w2t = [D][H]
    router_kernel<<<TT/8, 256>>>(x, wr, br, probs_out);

    cudaFuncSetAttribute(ffn_kernel, cudaFuncAttributeMaxDynamicSharedMemorySize, SMEM_BYTES);
    ffn_kernel<<<(2*TT)/BM + EE, 256, SMEM_BYTES>>>(x, b1, b2);

    combine_kernel<<<(TT*DD/4)/256, 256>>>(out);
}

// round 9
// speedup vs baseline: 8.4172x; 1.1415x over previous
#include <cuda_runtime.h>
#include <cuda_fp16.h>
#include <cstdint>
#include <math.h>

#define TT 16384
#define DD 256
#define HH 1024
#define EE 8
#define BM 64
#define HC 64
#define NCH (HH/HC)   // 16

// smem byte offsets (dynamic smem base)
#define XS_OFF  0u        // X:  64 rows x 512B, swizzled
#define W1_OFF  32768u    // W1c: 64 rows x 512B, swizzled   [n][k=256]
#define W2_OFF  65536u    // W2c: 256 rows x 144B (stride 72 halves) [n][k=64]
#define HS_OFF  102400u   // Hs: 64 rows x 144B
#define W2_S 72
#define HS_S 72
#define SMEM_BYTES 111616

// 16B-granule XOR swizzle for 512B rows (bits 4..6 ^= row&7)
#define SWZ512(byte, row) ((byte) ^ (((row) & 7) << 4))

__device__ int    g_counts[EE];
__device__ int    g_tok [EE*TT];
__device__ float  g_wt  [EE*TT];
__device__ int    g_slot[EE*TT];
__device__ float  g_contrib[2*TT*DD];
__device__ __half g_w1t[EE*HH*DD];   // [E][H][D] fp16
__device__ __half g_w2t[EE*DD*HH];   // [E][D][H] fp16

__device__ __forceinline__ uint32_t s2u(const void* p) {
    uint32_t a;
    asm("{ .reg .u64 t; cvta.to.shared.u64 t, %1; cvt.u32.u64 %0, t; }" : "=r"(a) : "l"(p));
    return a;
}
__device__ __forceinline__ void cpa16(uint32_t s, const void* g) {
    asm volatile("cp.async.cg.shared.global [%0], [%1], 16;" :: "r"(s), "l"(g));
}
#define CP_COMMIT() asm volatile("cp.async.commit_group;")
#define CP_WAIT0()  asm volatile("cp.async.wait_group 0;")

__device__ __forceinline__ void ldsm4(uint32_t& r0, uint32_t& r1, uint32_t& r2,
                                      uint32_t& r3, uint32_t a) {
    asm volatile("ldmatrix.sync.aligned.m8n8.x4.shared.b16 {%0,%1,%2,%3}, [%4];"
                 : "=r"(r0), "=r"(r1), "=r"(r2), "=r"(r3) : "r"(a));
}
__device__ __forceinline__ void mma16(float* c, const uint32_t* a,
                                      uint32_t b0, uint32_t b1) {
    asm volatile("mma.sync.aligned.m16n8k16.row.col.f32.f16.f16.f32 "
                 "{%0,%1,%2,%3}, {%4,%5,%6,%7}, {%8,%9}, {%0,%1,%2,%3};"
                 : "+f"(c[0]), "+f"(c[1]), "+f"(c[2]), "+f"(c[3])
                 : "r"(a[0]), "r"(a[1]), "r"(a[2]), "r"(a[3]), "r"(b0), "r"(b1));
}
// fast GELU: 0.5z(1+tanh(0.79788456(z+0.044715 z^3))) with MUFU tanh
__device__ __forceinline__ float gelu_f(float v) {
    float u = 0.7978845608f * fmaf(0.044715f * v, v * v, v);
    float t;
    asm("tanh.approx.f32 %0, %1;" : "=f"(t) : "f"(u));
    return 0.5f * v * (1.f + t);
}

// ---- fused transpose + fp16 convert for BOTH weights (blockIdx.z selects) --
__global__ __launch_bounds__(256) void transpose_kernel(
    const float* __restrict__ w1in, const float* __restrict__ w2in)
{
    __shared__ float tile[32][33];
    int which = blockIdx.z;
    const float* in = which ? w2in : w1in;
    __half* outp = which ? g_w2t : g_w1t;
    int M = which ? HH : DD;
    int N = which ? DD : HH;
    int ntj = N >> 5;
    int b = blockIdx.x, e = blockIdx.y;
    int ti = b / ntj, tj = b % ntj;
    const float* ine = in + (size_t)e * M * N;
    __half* oute = outp + (size_t)e * M * N;
    int c = threadIdx.x & 31, r8 = threadIdx.x >> 5;
#pragma unroll
    for (int it = 0; it < 4; it++) {
        int r = it * 8 + r8;
        tile[r][c] = __ldg(ine + (size_t)(ti*32 + r) * N + tj*32 + c);
    }
    __syncthreads();
#pragma unroll
    for (int it = 0; it < 4; it++) {
        int r = it * 8 + r8;
        oute[(size_t)(tj*32 + r) * M + ti*32 + c] = __float2half_rn(tile[c][r]);
    }
}

// ---------------- router: warp per token ------------------------------------
__global__ __launch_bounds__(256) void router_kernel(
    const float* __restrict__ x, const float* __restrict__ wr,
    const float* __restrict__ br, float* __restrict__ probs_out)
{
    int tid = threadIdx.x, lane = tid & 31;
    int t = (blockIdx.x * 256 + tid) >> 5;
    if (t >= TT) return;

    const float4* xr = (const float4*)(x + (size_t)t * DD + lane * 8);
    float4 x0 = __ldg(xr), x1 = __ldg(xr + 1);
    float xv[8] = {x0.x,x0.y,x0.z,x0.w,x1.x,x1.y,x1.z,x1.w};

    float l[EE];
#pragma unroll
    for (int e = 0; e < EE; e++) l[e] = 0.f;
    const float4* wrow = (const float4*)(wr + (size_t)(lane * 8) * EE);
#pragma unroll
    for (int j = 0; j < 8; j++) {
        float4 wa = __ldg(wrow + 2*j), wb = __ldg(wrow + 2*j + 1);
        l[0] = fmaf(xv[j], wa.x, l[0]); l[1] = fmaf(xv[j], wa.y, l[1]);
        l[2] = fmaf(xv[j], wa.z, l[2]); l[3] = fmaf(xv[j], wa.w, l[3]);
        l[4] = fmaf(xv[j], wb.x, l[4]); l[5] = fmaf(xv[j], wb.y, l[5]);
        l[6] = fmaf(xv[j], wb.z, l[6]); l[7] = fmaf(xv[j], wb.w, l[7]);
    }
#pragma unroll
    for (int off = 16; off > 0; off >>= 1)
#pragma unroll
        for (int e = 0; e < EE; e++) l[e] += __shfl_xor_sync(0xFFFFFFFF, l[e], off);

    if (lane) return;
#pragma unroll
    for (int e = 0; e < EE; e++) l[e] += __ldg(br + e);
    float mx = l[0];
#pragma unroll
    for (int e = 1; e < EE; e++) mx = fmaxf(mx, l[e]);
    float s = 0.f, p[EE];
#pragma unroll
    for (int e = 0; e < EE; e++) { p[e] = __expf(l[e] - mx); s += p[e]; }
    float inv = 1.f / s;
#pragma unroll
    for (int e = 0; e < EE; e++) p[e] *= inv;

    float4* po = (float4*)(probs_out + (size_t)t * EE);
    po[0] = make_float4(p[0],p[1],p[2],p[3]);
    po[1] = make_float4(p[4],p[5],p[6],p[7]);

    int i0 = 0; float v0 = p[0];
#pragma unroll
    for (int e = 1; e < EE; e++) if (p[e] > v0) { v0 = p[e]; i0 = e; }
    int i1 = -1; float v1 = -1.f;
#pragma unroll
    for (int e = 0; e < EE; e++) if (e != i0 && p[e] > v1) { v1 = p[e]; i1 = e; }
    float rs = 1.f / (v0 + v1);

    int p0 = atomicAdd(&g_counts[i0], 1);
    g_tok[i0*TT+p0] = t; g_wt[i0*TT+p0] = v0*rs; g_slot[i0*TT+p0] = 2*t;
    int p1 = atomicAdd(&g_counts[i1], 1);
    g_tok[i1*TT+p1] = t; g_wt[i1*TT+p1] = v1*rs; g_slot[i1*TT+p1] = 2*t+1;
}

// ---------------- FFN: fp16 mma.sync, HC=64, swizzled tiles -----------------
__global__ __launch_bounds__(256, 2) void ffn_kernel(
    const float* __restrict__ xg,
    const float* __restrict__ b1g, const float* __restrict__ b2g)
{
    extern __shared__ char sh[];
    __shared__ int toks[BM]; __shared__ float wts[BM]; __shared__ int slts[BM];

    int tid = threadIdx.x, wid = tid >> 5, lane = tid & 31;
    int qr = lane >> 2, qc = lane & 3;
    int wr = wid & 3, wc = wid >> 2;     // GEMM1: 4 M-groups x 2 N-halves
    int wr2 = wid & 1, wc2 = wid >> 1;   // GEMM2: 2 M-groups x 4 N-quarters

    int e = -1, tile = 0, cnt = 0, acc = 0;
#pragma unroll
    for (int i = 0; i < EE; i++) {
        int c = g_counts[i], nt = (c + BM - 1) / BM;
        if (e < 0 && (int)blockIdx.x < acc + nt) { e = i; tile = blockIdx.x - acc; cnt = c; }
        acc += nt;
    }
    if (e < 0) return;
    int base = tile * BM, mval = min(BM, cnt - base);

    if (tid < BM) {
        if (tid < mval) {
            toks[tid] = g_tok [e*TT + base + tid];
            wts [tid] = g_wt  [e*TT + base + tid];
            slts[tid] = g_slot[e*TT + base + tid];
        } else { toks[tid] = 0; wts[tid] = 0.f; slts[tid] = 0; }
    }
    __syncthreads();

    const __half* w1te = g_w1t + (size_t)e * HH * DD;   // [H][D]
    const __half* w2te = g_w2t + (size_t)e * DD * HH;   // [D][H]
    const float*  b1e  = b1g + (size_t)e * HH;
    const float*  b2e  = b2g + (size_t)e * DD;

    uint32_t smb = s2u(sh);
    uint32_t xs_b = smb + XS_OFF, w1_b = smb + W1_OFF;
    uint32_t w2_b = smb + W2_OFF, hs_b = smb + HS_OFF;

    // prologue: W1 chunk 0 (64 rows x 512B, swizzled)
#pragma unroll
    for (int i = 0; i < 8; i++) {
        int f = tid + i*256, row = f >> 5, seg = f & 31;
        cpa16(w1_b + (uint32_t)(row*512 + SWZ512(seg*16, row)),
              w1te + (size_t)row*DD + seg*8);
    }
    CP_COMMIT();
    // gather + cvt X [64,256] into swizzled rows
    for (int i4 = tid; i4 < BM*64; i4 += 256) {
        int r = i4 >> 6, c4 = i4 & 63;
        float4 v = (r < mval) ? __ldg((const float4*)(xg + (size_t)toks[r]*DD + c4*4))
                              : make_float4(0.f,0.f,0.f,0.f);
        __half2 h0 = __floats2half2_rn(v.x, v.y);
        __half2 h1 = __floats2half2_rn(v.z, v.w);
        uint2 u;
        u.x = *reinterpret_cast<uint32_t*>(&h0);
        u.y = *reinterpret_cast<uint32_t*>(&h1);
        *reinterpret_cast<uint2*>(sh + XS_OFF + r*512 + SWZ512(c4*8, r)) = u;
    }
    CP_WAIT0();
    __syncthreads();

    float c2[2][8][4];
#pragma unroll
    for (int mt = 0; mt < 2; mt++)
#pragma unroll
        for (int nt = 0; nt < 8; nt++)
#pragma unroll
            for (int c = 0; c < 4; c++) c2[mt][nt][c] = 0.f;

    int a_row = lane & 15, a_kof = 8 * (lane >> 4);
    int b_row = ((lane >> 4) << 3) + (lane & 7);
    int b_kof = 8 * ((lane >> 3) & 1);

    for (int hc = 0; hc < NCH; hc++) {
        // prefetch W2 chunk hc (256 rows x 128B, stride 144B)
#pragma unroll
        for (int i = 0; i < 8; i++) {
            int f = tid + i*256, row = f >> 3, seg = f & 7;
            cpa16(w2_b + (uint32_t)(row*(W2_S*2) + seg*16),
                  w2te + (size_t)row*HH + hc*HC + seg*8);
        }
        CP_COMMIT();

        // ---- GEMM1: C1[64,64] = X[64,256] @ W1c ; warp tile 16x32
        float c1[4][4];
#pragma unroll
        for (int nt = 0; nt < 4; nt++)
#pragma unroll
            for (int c = 0; c < 4; c++) c1[nt][c] = 0.f;

#pragma unroll
        for (int ks = 0; ks < 16; ks++) {
            int k0 = ks * 16;
            uint32_t a[4], b0[4], b1r[4];
            {
                int row = wr*16 + a_row;
                ldsm4(a[0],a[1],a[2],a[3],
                      xs_b + (uint32_t)(row*512 + SWZ512((k0 + a_kof)*2, row)));
            }
            {
                int row = wc*32 + b_row;
                ldsm4(b0[0],b0[1],b0[2],b0[3],
                      w1_b + (uint32_t)(row*512 + SWZ512((k0 + b_kof)*2, row)));
                row += 16;
                ldsm4(b1r[0],b1r[1],b1r[2],b1r[3],
                      w1_b + (uint32_t)(row*512 + SWZ512((k0 + b_kof)*2, row)));
            }
            mma16(c1[0], a, b0[0], b0[1]);
            mma16(c1[1], a, b0[2], b0[3]);
            mma16(c1[2], a, b1r[0], b1r[1]);
            mma16(c1[3], a, b1r[2], b1r[3]);
        }

        // ---- bias + fast GELU -> Hs (W2 cp.async still in flight)
#pragma unroll
        for (int nt = 0; nt < 4; nt++) {
            int col = wc*32 + nt*8 + 2*qc;
            float bb0 = __ldg(b1e + hc*HC + col);
            float bb1 = __ldg(b1e + hc*HC + col + 1);
            int r = wr*16 + qr;
            float v0 = gelu_f(c1[nt][0] + bb0), v1 = gelu_f(c1[nt][1] + bb1);
            float v2 = gelu_f(c1[nt][2] + bb0), v3 = gelu_f(c1[nt][3] + bb1);
            *reinterpret_cast<__half2*>(sh + HS_OFF + (r*HS_S + col)*2)
                = __floats2half2_rn(v0, v1);
            *reinterpret_cast<__half2*>(sh + HS_OFF + ((r+8)*HS_S + col)*2)
                = __floats2half2_rn(v2, v3);
        }
        CP_WAIT0();        // W2 chunk ready
        __syncthreads();   // Hs + W2 visible to all

        // prefetch W1 chunk hc+1 (overlaps GEMM2)
        if (hc + 1 < NCH) {
#pragma unroll
            for (int i = 0; i < 8; i++) {
                int f = tid + i*256, row = f >> 5, seg = f & 31;
                cpa16(w1_b + (uint32_t)(row*512 + SWZ512(seg*16, row)),
                      w1te + (size_t)((hc+1)*HC + row)*DD + seg*8);
            }
        }
        CP_COMMIT();

        // ---- GEMM2: C2[64,256] += H[64,64] @ W2c ; warp tile 32x64
#pragma unroll
        for (int ks = 0; ks < 4; ks++) {
            int k0 = ks * 16;
            uint32_t a0[4], a1[4];
            ldsm4(a0[0],a0[1],a0[2],a0[3],
                  hs_b + (uint32_t)(((wr2*32 + a_row)*HS_S + k0 + a_kof) * 2));
            ldsm4(a1[0],a1[1],a1[2],a1[3],
                  hs_b + (uint32_t)(((wr2*32 + 16 + a_row)*HS_S + k0 + a_kof) * 2));
#pragma unroll
            for (int p = 0; p < 4; p++) {
                uint32_t b[4];
                ldsm4(b[0],b[1],b[2],b[3],
                      w2_b + (uint32_t)(((wc2*64 + p*16 + b_row)*W2_S + k0 + b_kof) * 2));
                mma16(c2[0][2*p],   a0, b[0], b[1]);
                mma16(c2[0][2*p+1], a0, b[2], b[3]);
                mma16(c2[1][2*p],   a1, b[0], b[1]);
                mma16(c2[1][2*p+1], a1, b[2], b[3]);
            }
        }
        CP_WAIT0();    // W1 next ready
        __syncthreads();
    }

    // ---- epilogue: contrib[slot] = w * (y + b2)
#pragma unroll
    for (int mt = 0; mt < 2; mt++)
#pragma unroll
        for (int half = 0; half < 2; half++) {
            int r = wr2*32 + mt*16 + qr + half*8;
            if (r < mval) {
                float w = wts[r];
                float* crow = g_contrib + (size_t)slts[r] * DD;
#pragma unroll
                for (int nt = 0; nt < 8; nt++) {
                    int col = wc2*64 + nt*8 + 2*qc;
                    float2 o;
                    o.x = w * (c2[mt][nt][half*2+0] + __ldg(b2e + col));
                    o.y = w * (c2[mt][nt][half*2+1] + __ldg(b2e + col + 1));
                    *(float2*)(crow + col) = o;
                }
            }
        }
}

// ---------------- combine + counter reset -----------------------------------
__global__ __launch_bounds__(256) void combine_kernel(float* __restrict__ out)
{
    int g = blockIdx.x * 256 + threadIdx.x;
    int t = g >> 6, q = g & 63;
    const float4* c4 = (const float4*)g_contrib;
    float4 a = c4[(size_t)(2*t) * 64 + q];
    float4 b = c4[(size_t)(2*t+1) * 64 + q];
    ((float4*)out)[g] = make_float4(a.x+b.x, a.y+b.y, a.z+b.z, a.w+b.w);
    if (g < EE) g_counts[g] = 0;
}

extern "C" void kernel_launch(void* const* d_in, const int* in_sizes, int n_in,
                              void* d_out, int out_size)
{
    const float* x  = (const float*)d_in[0];
    const float* wr = (const float*)d_in[1];
    const float* br = (const float*)d_in[2];
    const float* w1 = (const float*)d_in[3];
    const float* b1 = (const float*)d_in[4];
    const float* w2 = (const float*)d_in[5];
    const float* b2 = (const float*)d_in[6];
    float* out = (float*)d_out;
    float* probs_out = out + (size_t)TT * DD;

    transpose_kernel<<<dim3(256, EE, 2), 256>>>(w1, w2);
    router_kernel<<<TT/8, 256>>>(x, wr, br, probs_out);

    cudaFuncSetAttribute(ffn_kernel, cudaFuncAttributeMaxDynamicSharedMemorySize, SMEM_BYTES);
    ffn_kernel<<<(2*TT)/BM + EE, 256, SMEM_BYTES>>>(x, b1, b2);

    combine_kernel<<<(TT*DD/4)/256, 256>>>(out);
}